// round 13
// baseline (speedup 1.0000x reference)
#include <cuda_runtime.h>
#include <cuda_fp16.h>
#include <cstdint>

// ---------------- problem constants ----------------
#define CB   8
#define CN   1024
#define CD   768
#define CH   12
#define CDKV 64
#define CDFF 3072
#define CE   16
#define CCAP 128
#define CBN  (CB*CN)          // 8192 tokens
#define CEC  (CE*CB*CCAP)     // 16384 expert slots
#define CMZ  (CB*CCAP)        // 1024 rows per expert
#define WSCALE 32.0f
#define WISCALE (1.0f/32.0f)

// ---------------- device scratch ----------------
static __device__ float g_h      [CBN*CD];
static __device__ float g_n2     [CBN*CD];
static __device__ float g_logits [CBN*CE];
static __device__ float g_raw    [CBN*CE];
static __device__ int   g_e1[CBN], g_e2[CBN], g_s1[CBN], g_s2[CBN];
static __device__ float g_g1[CBN], g_g2[CBN];
static __device__ int   g_cnt1[CB*CE];
static __device__ int   g_route[CEC];
static __device__ float g_xo [CEC*CD];
// split-fp16 activations
static __device__ __half g_nh [CBN*CD], g_nl [CBN*CD];     // normed hi/lo
static __device__ __half g_qh [CBN*CD], g_ql [CBN*CD];     // q hi/lo
static __device__ __half g_kh [CBN*CD], g_kl [CBN*CD];     // k hi/lo
static __device__ __half g_vh [CBN*CD], g_vl [CBN*CD];     // v hi/lo
static __device__ __half g_aoh[CBN*CD], g_aol[CBN*CD];     // attn out hi/lo
// fp16 projection weights, native [K][N], scaled by WSCALE, split hi/lo
static __device__ __half g_wqh[CD*CD], g_wql[CD*CD];
static __device__ __half g_wkh[CD*CD], g_wkl[CD*CD];
static __device__ __half g_wvh[CD*CD], g_wvl[CD*CD];
static __device__ __half g_woh[CD*CD], g_wol[CD*CD];
// fp16 MoE path (weights native [K][N])
static __device__ __half g_xinh[CEC*CD];
static __device__ __half g_midh[CEC*CDFF];
static __device__ __half g_w1h [CE*CD*CDFF];   // [e][D][DFF]
static __device__ __half g_w2h [CE*CDFF*CD];   // [e][DFF][D]

// ================= portable PTX helpers =================
__device__ __forceinline__ uint32_t smem_u32(const void* p) {
    uint32_t a;
    asm("{ .reg .u64 t; cvta.to.shared.u64 t, %1; cvt.u32.u64 %0, t; }" : "=r"(a) : "l"(p));
    return a;
}
#define CP16(dst, src) \
    asm volatile("cp.async.cg.shared.global [%0], [%1], 16;" :: "r"(dst), "l"(src) : "memory")
#define CPCOMMIT() asm volatile("cp.async.commit_group;" ::: "memory")
#define CPWAIT0()  asm volatile("cp.async.wait_group 0;" ::: "memory")
#define LDSM4(r0, r1, r2, r3, addr) \
    asm volatile("ldmatrix.sync.aligned.m8n8.x4.shared.b16 {%0,%1,%2,%3}, [%4];" \
        : "=r"(r0), "=r"(r1), "=r"(r2), "=r"(r3) : "r"(addr))
#define LDSM4T(r0, r1, r2, r3, addr) \
    asm volatile("ldmatrix.sync.aligned.m8n8.x4.trans.shared.b16 {%0,%1,%2,%3}, [%4];" \
        : "=r"(r0), "=r"(r1), "=r"(r2), "=r"(r3) : "r"(addr))
#define MMAH(c, a, b0v, b1v) \
    asm volatile("mma.sync.aligned.m16n8k16.row.col.f32.f16.f16.f32 " \
        "{%0,%1,%2,%3}, {%4,%5,%6,%7}, {%8,%9}, {%0,%1,%2,%3};" \
        : "+f"((c)[0]), "+f"((c)[1]), "+f"((c)[2]), "+f"((c)[3]) \
        : "r"((a)[0]), "r"((a)[1]), "r"((a)[2]), "r"((a)[3]), "r"(b0v), "r"(b1v))

// FMA-pipe exp (no MUFU): magic-number round + degree-6 2^f Taylor + exponent add.
__device__ __forceinline__ float fast_exp(float x) {
    x = fmaxf(x, -80.f);
    float t  = x * 1.44269504f;
    float tt = t + 12582912.f;
    int   ei = __float_as_int(tt) - 0x4B400000;
    float n  = tt - 12582912.f;
    float f  = t - n;
    float u  = f * 0.69314718f;
    float p  = 1.f + u*(1.f + u*(0.5f + u*(0.16666667f + u*(0.041666668f +
               u*(0.0083333338f + u*0.0013888889f)))));
    return __int_as_float(__float_as_int(p) + (ei << 23));
}

// ---------------- RMSNorm (T5, eps=1e-6); OUTMODE 0=fp32, 1=split fp16 ----------------
template<int OUTMODE>
__global__ void rmsnorm_kernel(const float* __restrict__ x,
                               const float* __restrict__ w,
                               float* __restrict__ y,
                               __half* __restrict__ yh,
                               __half* __restrict__ yl) {
    int row = blockIdx.x;
    const float* xr = x + (size_t)row * CD;
    float s = 0.f;
    for (int i = threadIdx.x; i < CD; i += 256) { float v = xr[i]; s = fmaf(v, v, s); }
    for (int o = 16; o; o >>= 1) s += __shfl_xor_sync(0xffffffffu, s, o);
    __shared__ float red[8];
    __shared__ float invs;
    if ((threadIdx.x & 31) == 0) red[threadIdx.x >> 5] = s;
    __syncthreads();
    if (threadIdx.x == 0) {
        float tot = 0.f;
        #pragma unroll
        for (int i = 0; i < 8; i++) tot += red[i];
        invs = rsqrtf(tot / CD + 1e-6f);
    }
    __syncthreads();
    float inv = invs;
    for (int i = threadIdx.x; i < CD; i += 256) {
        float v = xr[i] * inv * w[i];
        if (OUTMODE == 0) {
            y[(size_t)row*CD + i] = v;
        } else {
            __half hv = __float2half_rn(v);
            yh[(size_t)row*CD + i] = hv;
            yl[(size_t)row*CD + i] = __float2half_rn(v - __half2float(hv));
        }
    }
}

// ---------------- unified fp16 tensor-core GEMM (projections; 2-stage, static smem) ----------------
template<int TERMS, bool RELU, bool RESID, int OUTM>
__global__ __launch_bounds__(256) void mma_gemm(
    const __half* __restrict__ Ahi, const __half* __restrict__ Alo,
    const __half* __restrict__ Bhi, const __half* __restrict__ Blo,
    const float* __restrict__ Rz, void* __restrict__ Cout, void* __restrict__ Cout2,
    int Nn, int K, float scale, long zA, long zB, long zC)
{
    constexpr int BK    = (TERMS == 3) ? 16 : 32;
    constexpr int NA    = (TERMS == 3) ? 2 : 1;
    constexpr int LDSA  = BK + 8;
    constexpr int LDSB  = 136;
    constexpr uint32_t ATILEB = 128u * LDSA * 2;
    constexpr uint32_t BTILEB = (uint32_t)BK * LDSB * 2;
    constexpr uint32_t STAGEB = NA * (ATILEB + BTILEB);
    constexpr int ACH = 128 * (BK / 8);
    constexpr int BCH = BK * 16;
    constexpr int CPT = NA * (ACH + BCH) / 256;
    __shared__ __align__(16) unsigned char sm[2 * STAGEB];

    long e = blockIdx.z;
    int m0 = blockIdx.y * 128, n0 = blockIdx.x * 128;

    int tid = threadIdx.x, lane = tid & 31, wid = tid >> 5;
    int warp_row = (wid & 3) * 32, warp_col = (wid >> 2) * 64;
    uint32_t sb = smem_u32(sm);

    const __half* cur[CPT];
    long gstep[CPT];
    uint32_t sd[CPT];
    #pragma unroll
    for (int j = 0; j < CPT; j++) {
        int c = tid + j * 256;
        if (c < NA * ACH) {
            int tile = c / ACH;
            int rr = (c % ACH) / (BK / 8);
            int c8 = c % (BK / 8);
            sd[j] = tile * (ATILEB + BTILEB) + (uint32_t)(rr * LDSA + c8 * 8) * 2;
            const __half* src = (tile == 0 ? Ahi : Alo);
            cur[j] = src + e * zA + (long)(m0 + rr) * K + c8 * 8;
            gstep[j] = BK;
        } else {
            int c2 = c - NA * ACH;
            int tile = c2 / BCH;
            int rr = (c2 % BCH) / 16;
            int c8 = c2 % 16;
            sd[j] = tile * (ATILEB + BTILEB) + ATILEB + (uint32_t)(rr * LDSB + c8 * 8) * 2;
            const __half* src = (tile == 0 ? Bhi : Blo);
            cur[j] = src + e * zB + (long)rr * Nn + n0 + c8 * 8;
            gstep[j] = (long)BK * Nn;
        }
    }

    int nk = K / BK;
    #pragma unroll
    for (int j = 0; j < CPT; j++) { CP16(sb + sd[j], cur[j]); cur[j] += gstep[j]; }
    CPCOMMIT();

    float acc[2][8][4];
    #pragma unroll
    for (int mi = 0; mi < 2; mi++)
        #pragma unroll
        for (int ni = 0; ni < 8; ni++)
            #pragma unroll
            for (int j = 0; j < 4; j++) acc[mi][ni][j] = 0.f;

    int lm_r = lane & 15, lm_k = (lane >> 4) << 3;

    for (int kc = 0; kc < nk; kc++) {
        CPWAIT0();
        __syncthreads();
        if (kc + 1 < nk) {
            uint32_t s2 = (uint32_t)((kc + 1) & 1) * STAGEB;
            #pragma unroll
            for (int j = 0; j < CPT; j++) { CP16(sb + s2 + sd[j], cur[j]); cur[j] += gstep[j]; }
            CPCOMMIT();
        }
        uint32_t st = sb + (uint32_t)(kc & 1) * STAGEB;
        #pragma unroll
        for (int k16 = 0; k16 < BK; k16 += 16) {
            uint32_t afh[2][4], afl[2][4];
            #pragma unroll
            for (int mi = 0; mi < 2; mi++) {
                int row = warp_row + mi*16 + lm_r;
                LDSM4(afh[mi][0], afh[mi][1], afh[mi][2], afh[mi][3],
                      st + (uint32_t)(row*LDSA + k16 + lm_k) * 2);
                if (TERMS == 3)
                    LDSM4(afl[mi][0], afl[mi][1], afl[mi][2], afl[mi][3],
                          st + (ATILEB + BTILEB) + (uint32_t)(row*LDSA + k16 + lm_k) * 2);
            }
            #pragma unroll
            for (int nt = 0; nt < 4; nt++) {
                uint32_t boff = (uint32_t)((k16 + lm_r) * LDSB + warp_col + nt*16 + lm_k) * 2;
                uint32_t bh[4], bl[4];
                LDSM4T(bh[0], bh[1], bh[2], bh[3], st + ATILEB + boff);
                if (TERMS == 3)
                    LDSM4T(bl[0], bl[1], bl[2], bl[3],
                           st + (ATILEB + BTILEB) + ATILEB + boff);
                #pragma unroll
                for (int mi = 0; mi < 2; mi++)
                    #pragma unroll
                    for (int hh = 0; hh < 2; hh++) {
                        float* cc = acc[mi][nt*2 + hh];
                        MMAH(cc, afh[mi], bh[2*hh], bh[2*hh + 1]);
                        if (TERMS == 3) {
                            MMAH(cc, afh[mi], bl[2*hh], bl[2*hh + 1]);
                            MMAH(cc, afl[mi], bh[2*hh], bh[2*hh + 1]);
                        }
                    }
            }
        }
    }

    int eg = lane >> 2, et = lane & 3;
    #pragma unroll
    for (int mi = 0; mi < 2; mi++) {
        #pragma unroll
        for (int ni = 0; ni < 8; ni++) {
            long r  = m0 + warp_row + mi*16 + eg;
            long cc = n0 + warp_col + ni*8 + et*2;
            float v0 = acc[mi][ni][0]*scale, v1 = acc[mi][ni][1]*scale;
            float v2 = acc[mi][ni][2]*scale, v3 = acc[mi][ni][3]*scale;
            if (RESID) {
                float2 r0 = *(const float2*)(Rz + r*Nn + cc);
                float2 r1 = *(const float2*)(Rz + (r+8)*Nn + cc);
                v0 += r0.x; v1 += r0.y; v2 += r1.x; v3 += r1.y;
            }
            if (RELU) {
                v0 = fmaxf(v0, 0.f); v1 = fmaxf(v1, 0.f);
                v2 = fmaxf(v2, 0.f); v3 = fmaxf(v3, 0.f);
            }
            if (OUTM == 0) {
                float* C = (float*)Cout + e*zC;
                *(float2*)(C + r*Nn + cc)     = make_float2(v0, v1);
                *(float2*)(C + (r+8)*Nn + cc) = make_float2(v2, v3);
            } else if (OUTM == 1) {
                __half* C = (__half*)Cout + e*zC;
                *(__half2*)(C + r*Nn + cc)     = __floats2half2_rn(v0, v1);
                *(__half2*)(C + (r+8)*Nn + cc) = __floats2half2_rn(v2, v3);
            } else {
                __half* C  = (__half*)Cout  + e*zC;
                __half* C2 = (__half*)Cout2 + e*zC;
                __half2 h0 = __floats2half2_rn(v0, v1);
                float2 f0 = __half22float2(h0);
                *(__half2*)(C  + r*Nn + cc) = h0;
                *(__half2*)(C2 + r*Nn + cc) = __floats2half2_rn(v0 - f0.x, v1 - f0.y);
                __half2 h1 = __floats2half2_rn(v2, v3);
                float2 f1 = __half22float2(h1);
                *(__half2*)(C  + (r+8)*Nn + cc) = h1;
                *(__half2*)(C2 + (r+8)*Nn + cc) = __floats2half2_rn(v2 - f1.x, v3 - f1.y);
            }
        }
    }
}

// ---------------- MoE FFN GEMM: 256x128 CTA tile, 64x64 per warp ----------------
// C[M,Nn] per expert = A[M,K] @ B[K,Nn] (+relu), fp32 accum, fp16 or fp32 out.
// Same BK=32 / k16 accumulation order as mma_gemm -> bit-identical results.
template<bool RELU, bool OUTH>
__global__ __launch_bounds__(256) void moe_gemm256(
    const __half* __restrict__ A, const __half* __restrict__ Bw,
    void* __restrict__ Cout, int Nn, int K, long zA, long zB, long zC)
{
    constexpr int BK   = 32;
    constexpr int LDSA = 40;
    constexpr int LDSB = 136;
    constexpr uint32_t ATILEB = 256u * LDSA * 2;   // 20480
    constexpr uint32_t BTILEB = 32u * LDSB * 2;    // 8704
    constexpr uint32_t STAGEB = ATILEB + BTILEB;   // 29184
    extern __shared__ __align__(16) unsigned char sm[];

    long e = blockIdx.z;
    int m0 = blockIdx.y * 256, n0 = blockIdx.x * 128;

    int tid = threadIdx.x, lane = tid & 31, wid = tid >> 5;
    int warp_row = (wid & 3) * 64, warp_col = (wid >> 2) * 64;
    uint32_t sb = smem_u32(sm);

    // loader: 1024 A chunks + 512 B chunks of 16B = 6 per thread
    const __half* cur[6];
    long gstep[6];
    uint32_t sd[6];
    #pragma unroll
    for (int j = 0; j < 6; j++) {
        int c = tid + j * 256;
        if (c < 1024) {
            int rr = c >> 2, c8 = (c & 3) * 8;
            sd[j] = (uint32_t)(rr * LDSA + c8) * 2;
            cur[j] = A + e * zA + (long)(m0 + rr) * K + c8;
            gstep[j] = BK;
        } else {
            int c2 = c - 1024;
            int rr = c2 >> 4, c8 = (c2 & 15) * 8;
            sd[j] = ATILEB + (uint32_t)(rr * LDSB + c8) * 2;
            cur[j] = Bw + e * zB + (long)rr * Nn + n0 + c8;
            gstep[j] = (long)BK * Nn;
        }
    }

    int nk = K / BK;
    #pragma unroll
    for (int j = 0; j < 6; j++) { CP16(sb + sd[j], cur[j]); cur[j] += gstep[j]; }
    CPCOMMIT();

    float acc[4][8][4];
    #pragma unroll
    for (int mi = 0; mi < 4; mi++)
        #pragma unroll
        for (int ni = 0; ni < 8; ni++)
            #pragma unroll
            for (int j = 0; j < 4; j++) acc[mi][ni][j] = 0.f;

    int lm_r = lane & 15, lm_k = (lane >> 4) << 3;

    for (int kc = 0; kc < nk; kc++) {
        CPWAIT0();
        __syncthreads();
        if (kc + 1 < nk) {
            uint32_t s2 = (uint32_t)((kc + 1) & 1) * STAGEB;
            #pragma unroll
            for (int j = 0; j < 6; j++) { CP16(sb + s2 + sd[j], cur[j]); cur[j] += gstep[j]; }
            CPCOMMIT();
        }
        uint32_t st = sb + (uint32_t)(kc & 1) * STAGEB;
        #pragma unroll
        for (int k16 = 0; k16 < BK; k16 += 16) {
            uint32_t af[4][4];
            #pragma unroll
            for (int mi = 0; mi < 4; mi++) {
                int row = warp_row + mi*16 + lm_r;
                LDSM4(af[mi][0], af[mi][1], af[mi][2], af[mi][3],
                      st + (uint32_t)(row*LDSA + k16 + lm_k) * 2);
            }
            #pragma unroll
            for (int nt = 0; nt < 4; nt++) {
                uint32_t boff = (uint32_t)((k16 + lm_r) * LDSB + warp_col + nt*16 + lm_k) * 2;
                uint32_t bh[4];
                LDSM4T(bh[0], bh[1], bh[2], bh[3], st + ATILEB + boff);
                #pragma unroll
                for (int mi = 0; mi < 4; mi++)
                    #pragma unroll
                    for (int hh = 0; hh < 2; hh++)
                        MMAH(acc[mi][nt*2 + hh], af[mi], bh[2*hh], bh[2*hh + 1]);
            }
        }
    }

    int eg = lane >> 2, et = lane & 3;
    #pragma unroll
    for (int mi = 0; mi < 4; mi++) {
        #pragma unroll
        for (int ni = 0; ni < 8; ni++) {
            long r  = m0 + warp_row + mi*16 + eg;
            long cc = n0 + warp_col + ni*8 + et*2;
            float v0 = acc[mi][ni][0], v1 = acc[mi][ni][1];
            float v2 = acc[mi][ni][2], v3 = acc[mi][ni][3];
            if (RELU) {
                v0 = fmaxf(v0, 0.f); v1 = fmaxf(v1, 0.f);
                v2 = fmaxf(v2, 0.f); v3 = fmaxf(v3, 0.f);
            }
            if (OUTH) {
                __half* C = (__half*)Cout + e*zC;
                *(__half2*)(C + r*Nn + cc)     = __floats2half2_rn(v0, v1);
                *(__half2*)(C + (r+8)*Nn + cc) = __floats2half2_rn(v2, v3);
            } else {
                float* C = (float*)Cout + e*zC;
                *(float2*)(C + r*Nn + cc)     = make_float2(v0, v1);
                *(float2*)(C + (r+8)*Nn + cc) = make_float2(v2, v3);
            }
        }
    }
}
#define MOE256_SMEM (2 * ((256*40*2) + (32*136*2)))   // 58368

// ---------------- tensor-core flash attention (split-fp16 3-term, FMA-pipe exp) ----------------
__global__ __launch_bounds__(256) void tc_attn(const int* __restrict__ mask) {
    extern __shared__ __align__(16) unsigned char sm[];
    constexpr uint32_t LDQ = 72;
    constexpr uint32_t QT  = 128*LDQ*2;
    constexpr uint32_t KVT = 64*LDQ*2;
    constexpr uint32_t KVS = 4*KVT;
    constexpr uint32_t KVB = 2*QT;
    constexpr uint32_t MBB = KVB + 2*KVS;

    int tid = threadIdx.x, lane = tid & 31, w = tid >> 5;
    int g = lane >> 2, t4 = lane & 3;
    int lm_r = lane & 15, lm_k = (lane >> 4) << 3;
    int bh = blockIdx.y, b = bh / CH, hh = bh % CH;
    int q0 = blockIdx.x * 128;
    uint32_t sb = smem_u32(sm);
    float* MBf = (float*)(sm + MBB);

    for (int i = tid; i < CN; i += 256)
        MBf[i] = (mask[b*CN + i] != 0) ? 0.f : -1e9f;

    #pragma unroll
    for (int j = 0; j < 8; j++) {
        int c = tid + j*256;
        int arr = c >> 10, idx = c & 1023;
        int row = idx >> 3, ch = idx & 7;
        const __half* src = (arr ? g_ql : g_qh) + ((size_t)(b*CN + q0 + row)*CH + hh)*CDKV + ch*8;
        CP16(sb + (uint32_t)arr*QT + (uint32_t)(row*LDQ + ch*8)*2, src);
    }
    #pragma unroll
    for (int j = 0; j < 8; j++) {
        int c = tid + j*256;
        int arr = c >> 9, idx = c & 511;
        int row = idx >> 3, ch = idx & 7;
        const __half* src = (arr==0 ? g_kh : arr==1 ? g_kl : arr==2 ? g_vh : g_vl)
                          + ((size_t)(b*CN + row)*CH + hh)*CDKV + ch*8;
        CP16(sb + KVB + (uint32_t)arr*KVT + (uint32_t)(row*LDQ + ch*8)*2, src);
    }
    CPCOMMIT();
    CPWAIT0();
    __syncthreads();

    uint32_t qfh[4][4], qfl[4][4];
    #pragma unroll
    for (int kc = 0; kc < 4; kc++) {
        uint32_t a = sb + (uint32_t)((w*16 + lm_r)*LDQ + kc*16 + lm_k)*2;
        LDSM4(qfh[kc][0], qfh[kc][1], qfh[kc][2], qfh[kc][3], a);
        LDSM4(qfl[kc][0], qfl[kc][1], qfl[kc][2], qfl[kc][3], a + QT);
    }

    float m_lo = -1e30f, m_hi = -1e30f, l_lo = 0.f, l_hi = 0.f;
    float o[8][4];
    #pragma unroll
    for (int nd = 0; nd < 8; nd++)
        #pragma unroll
        for (int j = 0; j < 4; j++) o[nd][j] = 0.f;

    for (int kt = 0; kt < 16; kt++) {
        if (kt > 0) { CPWAIT0(); __syncthreads(); }
        if (kt + 1 < 16) {
            uint32_t s2 = (uint32_t)((kt+1) & 1) * KVS;
            #pragma unroll
            for (int j = 0; j < 8; j++) {
                int c = tid + j*256;
                int arr = c >> 9, idx = c & 511;
                int row = idx >> 3, ch = idx & 7;
                const __half* src = (arr==0 ? g_kh : arr==1 ? g_kl : arr==2 ? g_vh : g_vl)
                                  + ((size_t)(b*CN + (kt+1)*64 + row)*CH + hh)*CDKV + ch*8;
                CP16(sb + KVB + s2 + (uint32_t)arr*KVT + (uint32_t)(row*LDQ + ch*8)*2, src);
            }
            CPCOMMIT();
        }
        uint32_t kb = sb + KVB + (uint32_t)(kt & 1) * KVS;

        float cs[8][4];
        #pragma unroll
        for (int ni = 0; ni < 8; ni++)
            #pragma unroll
            for (int j = 0; j < 4; j++) cs[ni][j] = 0.f;
        #pragma unroll
        for (int kc = 0; kc < 4; kc++) {
            #pragma unroll
            for (int nt = 0; nt < 4; nt++) {
                uint32_t ka = kb + (uint32_t)((nt*16 + lm_r)*LDQ + kc*16 + lm_k)*2;
                uint32_t kfh[4], kfl[4];
                LDSM4(kfh[0], kfh[1], kfh[2], kfh[3], ka);
                LDSM4(kfl[0], kfl[1], kfl[2], kfl[3], ka + KVT);
                #pragma unroll
                for (int hx = 0; hx < 2; hx++) {
                    float* cc = cs[nt*2 + hx];
                    MMAH(cc, qfh[kc], kfh[hx], kfh[2+hx]);
                    MMAH(cc, qfh[kc], kfl[hx], kfl[2+hx]);
                    MMAH(cc, qfl[kc], kfh[hx], kfh[2+hx]);
                }
            }
        }
        float tl = -1e30f, th = -1e30f;
        #pragma unroll
        for (int ni = 0; ni < 8; ni++) {
            float b0 = MBf[kt*64 + ni*8 + 2*t4];
            float b1 = MBf[kt*64 + ni*8 + 2*t4 + 1];
            cs[ni][0] += b0; cs[ni][1] += b1; cs[ni][2] += b0; cs[ni][3] += b1;
            tl = fmaxf(tl, fmaxf(cs[ni][0], cs[ni][1]));
            th = fmaxf(th, fmaxf(cs[ni][2], cs[ni][3]));
        }
        tl = fmaxf(tl, __shfl_xor_sync(0xffffffffu, tl, 1));
        tl = fmaxf(tl, __shfl_xor_sync(0xffffffffu, tl, 2));
        th = fmaxf(th, __shfl_xor_sync(0xffffffffu, th, 1));
        th = fmaxf(th, __shfl_xor_sync(0xffffffffu, th, 2));
        float mn_lo = fmaxf(m_lo, tl), mn_hi = fmaxf(m_hi, th);
        float sc_lo = fast_exp(m_lo - mn_lo), sc_hi = fast_exp(m_hi - mn_hi);
        m_lo = mn_lo; m_hi = mn_hi;
        l_lo *= sc_lo; l_hi *= sc_hi;
        #pragma unroll
        for (int nd = 0; nd < 8; nd++) {
            o[nd][0] *= sc_lo; o[nd][1] *= sc_lo;
            o[nd][2] *= sc_hi; o[nd][3] *= sc_hi;
        }
        uint32_t pfh[4][4], pfl[4][4];
        #pragma unroll
        for (int j = 0; j < 4; j++) {
            float a0 = fast_exp(cs[2*j][0] - mn_lo),   a1 = fast_exp(cs[2*j][1] - mn_lo);
            float a2 = fast_exp(cs[2*j][2] - mn_hi),   a3 = fast_exp(cs[2*j][3] - mn_hi);
            float b0 = fast_exp(cs[2*j+1][0] - mn_lo), b1 = fast_exp(cs[2*j+1][1] - mn_lo);
            float b2 = fast_exp(cs[2*j+1][2] - mn_hi), b3 = fast_exp(cs[2*j+1][3] - mn_hi);
            l_lo += (a0 + a1) + (b0 + b1);
            l_hi += (a2 + a3) + (b2 + b3);
            __half2 h; float2 f;
            h = __floats2half2_rn(a0, a1); f = __half22float2(h);
            pfh[j][0] = *(uint32_t*)&h;
            { __half2 lo2 = __floats2half2_rn(a0 - f.x, a1 - f.y); pfl[j][0] = *(uint32_t*)&lo2; }
            h = __floats2half2_rn(a2, a3); f = __half22float2(h);
            pfh[j][1] = *(uint32_t*)&h;
            { __half2 lo2 = __floats2half2_rn(a2 - f.x, a3 - f.y); pfl[j][1] = *(uint32_t*)&lo2; }
            h = __floats2half2_rn(b0, b1); f = __half22float2(h);
            pfh[j][2] = *(uint32_t*)&h;
            { __half2 lo2 = __floats2half2_rn(b0 - f.x, b1 - f.y); pfl[j][2] = *(uint32_t*)&lo2; }
            h = __floats2half2_rn(b2, b3); f = __half22float2(h);
            pfh[j][3] = *(uint32_t*)&h;
            { __half2 lo2 = __floats2half2_rn(b2 - f.x, b3 - f.y); pfl[j][3] = *(uint32_t*)&lo2; }
        }
        #pragma unroll
        for (int j = 0; j < 4; j++) {
            #pragma unroll
            for (int nt = 0; nt < 4; nt++) {
                uint32_t va = kb + 2*KVT + (uint32_t)((j*16 + lm_r)*LDQ + nt*16 + lm_k)*2;
                uint32_t vfh[4], vfl[4];
                LDSM4T(vfh[0], vfh[1], vfh[2], vfh[3], va);
                LDSM4T(vfl[0], vfl[1], vfl[2], vfl[3], va + KVT);
                #pragma unroll
                for (int hx = 0; hx < 2; hx++) {
                    float* cc = o[nt*2 + hx];
                    MMAH(cc, pfh[j], vfh[2*hx], vfh[2*hx+1]);
                    MMAH(cc, pfh[j], vfl[2*hx], vfl[2*hx+1]);
                    MMAH(cc, pfl[j], vfh[2*hx], vfh[2*hx+1]);
                }
            }
        }
    }

    l_lo += __shfl_xor_sync(0xffffffffu, l_lo, 1);
    l_lo += __shfl_xor_sync(0xffffffffu, l_lo, 2);
    l_hi += __shfl_xor_sync(0xffffffffu, l_hi, 1);
    l_hi += __shfl_xor_sync(0xffffffffu, l_hi, 2);
    float il = 1.f / l_lo, ih = 1.f / l_hi;
    int r_lo = q0 + w*16 + g, r_hi = r_lo + 8;
    #pragma unroll
    for (int nd = 0; nd < 8; nd++) {
        int col = nd*8 + 2*t4;
        size_t o_lo = ((size_t)(b*CN + r_lo)*CH + hh)*CDKV + col;
        size_t o_hi = ((size_t)(b*CN + r_hi)*CH + hh)*CDKV + col;
        float v0 = o[nd][0]*il, v1 = o[nd][1]*il;
        float v2 = o[nd][2]*ih, v3 = o[nd][3]*ih;
        __half2 h0 = __floats2half2_rn(v0, v1);
        float2 f0 = __half22float2(h0);
        *(__half2*)(g_aoh + o_lo) = h0;
        *(__half2*)(g_aol + o_lo) = __floats2half2_rn(v0 - f0.x, v1 - f0.y);
        __half2 h1 = __floats2half2_rn(v2, v3);
        float2 f1 = __half22float2(h1);
        *(__half2*)(g_aoh + o_hi) = h1;
        *(__half2*)(g_aol + o_hi) = __floats2half2_rn(v2 - f1.x, v3 - f1.y);
    }
}
#define TCATTN_SMEM (2*(128*72*2) + 2*4*(64*72*2) + 1024*4)

// ---------------- gate logits (fp32: routing exactness) ----------------
__global__ void logits_kernel(const float* __restrict__ gw) {
    int tid = threadIdx.x;
    int tok = blockIdx.x * 16 + (tid >> 4);
    int e = tid & 15;
    const float* xr = g_n2 + (size_t)tok * CD;
    float acc = 0.f;
    #pragma unroll 8
    for (int d = 0; d < CD; d++) acc = fmaf(xr[d], gw[d*CE + e], acc);
    g_logits[(size_t)tok*CE + e] = acc;
}

// ---------------- gating: softmax + top2 ----------------
__global__ void gate_kernel() {
    int t = blockIdx.x * 256 + threadIdx.x;
    if (t >= CBN) return;
    float lg[CE];
    float mx = -1e30f;
    #pragma unroll
    for (int e = 0; e < CE; e++) { lg[e] = g_logits[(size_t)t*CE + e]; mx = fmaxf(mx, lg[e]); }
    float sum = 0.f;
    #pragma unroll
    for (int e = 0; e < CE; e++) { lg[e] = __expf(lg[e] - mx); sum += lg[e]; }
    float inv = 1.f / sum;
    #pragma unroll
    for (int e = 0; e < CE; e++) { lg[e] *= inv; g_raw[(size_t)t*CE + e] = lg[e]; }
    int i1 = 0; float b1 = lg[0];
    #pragma unroll
    for (int e = 1; e < CE; e++) if (lg[e] > b1) { b1 = lg[e]; i1 = e; }
    int i2 = -1; float b2 = -1.f;
    #pragma unroll
    for (int e = 0; e < CE; e++) if (e != i1 && lg[e] > b2) { b2 = lg[e]; i2 = e; }
    float denom = b1 + b2 + 1e-9f;
    g_e1[t] = i1; g_e2[t] = i2;
    g_g1[t] = b1 / denom; g_g2[t] = b2 / denom;
}

// ---------------- route init ----------------
__global__ void routeinit_kernel() {
    int i = blockIdx.x * 256 + threadIdx.x;
    if (i < CEC) g_route[i] = -1;
}

// ---------------- capacity assignment (sequential per (b,e)) ----------------
__global__ void capacity_kernel() {
    int b = blockIdx.x;
    int e = threadIdx.x;
    if (e >= CE) return;
    int cnt = 0;
    for (int n = 0; n < CN; n++) {
        int t = b*CN + n;
        if (g_e1[t] == e) {
            int pos = cnt++;
            if (pos < CCAP) {
                g_s1[t] = pos;
                g_route[(e*CB + b)*CCAP + pos] = t;
            } else {
                g_s1[t] = -1;
                g_g1[t] = 0.f;
            }
        }
    }
    g_cnt1[b*CE + e] = cnt;
    int m1c = cnt < CCAP ? cnt : CCAP;
    int cnt2 = 0;
    for (int n = 0; n < CN; n++) {
        int t = b*CN + n;
        if (g_e2[t] == e) {
            int pos = cnt2++ + m1c;
            if (pos < CCAP) {
                g_s2[t] = pos;
                g_route[(e*CB + b)*CCAP + pos] = t;
            } else {
                g_s2[t] = -1;
                g_g2[t] = 0.f;
            }
        }
    }
}

// ---------------- gather tokens into expert slots (fp16 out) ----------------
__global__ void gather_h_kernel() {
    int row = blockIdx.x;
    int t = g_route[row];
    __half2* dst = (__half2*)(g_xinh + (size_t)row * CD);
    int i = threadIdx.x;
    if (t < 0) {
        __half2 z = __floats2half2_rn(0.f, 0.f);
        dst[2*i] = z; dst[2*i+1] = z;
    } else {
        float4 v = ((const float4*)(g_n2 + (size_t)t * CD))[i];
        dst[2*i]   = __floats2half2_rn(v.x, v.y);
        dst[2*i+1] = __floats2half2_rn(v.z, v.w);
    }
}

// ---------------- streaming fp32 -> fp16 convert ----------------
template<bool SPLIT>
__global__ void convert_kernel(const float* __restrict__ in,
                               __half* __restrict__ hi,
                               __half* __restrict__ lo,
                               long n4, float scale) {
    long i = (long)blockIdx.x * blockDim.x + threadIdx.x;
    long stride = (long)gridDim.x * blockDim.x;
    for (; i < n4; i += stride) {
        float4 v = ((const float4*)in)[i];
        v.x *= scale; v.y *= scale; v.z *= scale; v.w *= scale;
        __half2 h0 = __floats2half2_rn(v.x, v.y);
        __half2 h1 = __floats2half2_rn(v.z, v.w);
        ((__half2*)hi)[2*i]   = h0;
        ((__half2*)hi)[2*i+1] = h1;
        if (SPLIT) {
            float2 f0 = __half22float2(h0), f1 = __half22float2(h1);
            ((__half2*)lo)[2*i]   = __floats2half2_rn(v.x - f0.x, v.y - f0.y);
            ((__half2*)lo)[2*i+1] = __floats2half2_rn(v.z - f1.x, v.w - f1.y);
        }
    }
}

// ---------------- weighted combine + residual 2 ----------------
__global__ void combine_kernel(float* __restrict__ out) {
    int t = blockIdx.x;
    int b = t / CN;
    const float4* hh = (const float4*)(g_h + (size_t)t * CD);
    float4 v = hh[threadIdx.x];
    int s1 = g_s1[t];
    if (s1 >= 0) {
        float gg = g_g1[t];
        const float4* x1 = (const float4*)(g_xo + ((size_t)(g_e1[t]*CB + b)*CCAP + s1) * CD);
        float4 a = x1[threadIdx.x];
        v.x = fmaf(gg, a.x, v.x); v.y = fmaf(gg, a.y, v.y);
        v.z = fmaf(gg, a.z, v.z); v.w = fmaf(gg, a.w, v.w);
    }
    int s2 = g_s2[t];
    if (s2 >= 0) {
        float gg = g_g2[t];
        const float4* x2 = (const float4*)(g_xo + ((size_t)(g_e2[t]*CB + b)*CCAP + s2) * CD);
        float4 a = x2[threadIdx.x];
        v.x = fmaf(gg, a.x, v.x); v.y = fmaf(gg, a.y, v.y);
        v.z = fmaf(gg, a.z, v.z); v.w = fmaf(gg, a.w, v.w);
    }
    ((float4*)out)[(size_t)t * (CD/4) + threadIdx.x] = v;
}

// ---------------- aux loss ----------------
__global__ void loss_kernel(float* __restrict__ out, int out_size) {
    int tid = threadIdx.x;
    int b = tid >> 4, e = tid & 15;
    float proxy = 0.f;
    for (int n = 0; n < CN; n++) proxy += g_raw[((size_t)(b*CN + n))*CE + e];
    proxy /= (float)CN;
    float dens = (float)g_cnt1[b*CE + e] / (float)CN;
    float v = proxy * dens;
    __shared__ float red[128];
    red[tid] = v;
    __syncthreads();
    for (int s = 64; s; s >>= 1) {
        if (tid < s) red[tid] += red[tid + s];
        __syncthreads();
    }
    if (tid == 0) {
        float loss = red[0] / (float)(CB*CE) * (float)(CE*CE) * 0.01f;
        const int base = CBN*CD;
        if (out_size > base) out[base] = loss;
        for (int i = base + 1; i < out_size; i++) out[i] = 0.f;
    }
}

// ---------------- launcher ----------------
extern "C" void kernel_launch(void* const* d_in, const int* in_sizes, int n_in,
                              void* d_out, int out_size) {
    const float* hid   = (const float*)d_in[0];
    const int*   mask  = (const int*)d_in[1];
    const float* ln0   = (const float*)d_in[2];
    const float* Wq    = (const float*)d_in[3];
    const float* Wk    = (const float*)d_in[4];
    const float* Wv    = (const float*)d_in[5];
    const float* Wo    = (const float*)d_in[6];
    const float* ln1   = (const float*)d_in[7];
    const float* gw    = (const float*)d_in[8];
    const float* ew1   = (const float*)d_in[9];
    const float* ew2   = (const float*)d_in[10];
    float* out = (float*)d_out;

    float *p_h, *p_n2, *p_xo;
    __half *p_nh, *p_nl, *p_qh, *p_ql, *p_kh, *p_kl, *p_vh, *p_vl, *p_aoh, *p_aol;
    __half *p_wqh, *p_wql, *p_wkh, *p_wkl, *p_wvh, *p_wvl, *p_woh, *p_wol;
    __half *p_xinh, *p_midh, *p_w1h, *p_w2h;
    cudaGetSymbolAddress((void**)&p_h,    g_h);
    cudaGetSymbolAddress((void**)&p_n2,   g_n2);
    cudaGetSymbolAddress((void**)&p_xo,   g_xo);
    cudaGetSymbolAddress((void**)&p_nh,   g_nh);
    cudaGetSymbolAddress((void**)&p_nl,   g_nl);
    cudaGetSymbolAddress((void**)&p_qh,   g_qh);
    cudaGetSymbolAddress((void**)&p_ql,   g_ql);
    cudaGetSymbolAddress((void**)&p_kh,   g_kh);
    cudaGetSymbolAddress((void**)&p_kl,   g_kl);
    cudaGetSymbolAddress((void**)&p_vh,   g_vh);
    cudaGetSymbolAddress((void**)&p_vl,   g_vl);
    cudaGetSymbolAddress((void**)&p_aoh,  g_aoh);
    cudaGetSymbolAddress((void**)&p_aol,  g_aol);
    cudaGetSymbolAddress((void**)&p_wqh,  g_wqh);
    cudaGetSymbolAddress((void**)&p_wql,  g_wql);
    cudaGetSymbolAddress((void**)&p_wkh,  g_wkh);
    cudaGetSymbolAddress((void**)&p_wkl,  g_wkl);
    cudaGetSymbolAddress((void**)&p_wvh,  g_wvh);
    cudaGetSymbolAddress((void**)&p_wvl,  g_wvl);
    cudaGetSymbolAddress((void**)&p_woh,  g_woh);
    cudaGetSymbolAddress((void**)&p_wol,  g_wol);
    cudaGetSymbolAddress((void**)&p_xinh, g_xinh);
    cudaGetSymbolAddress((void**)&p_midh, g_midh);
    cudaGetSymbolAddress((void**)&p_w1h,  g_w1h);
    cudaGetSymbolAddress((void**)&p_w2h,  g_w2h);

    // opt-in dynamic smem (attribute sets; not stream ops)
    cudaFuncSetAttribute(tc_attn, cudaFuncAttributeMaxDynamicSharedMemorySize, TCATTN_SMEM);
    cudaFuncSetAttribute(moe_gemm256<true,true>,   cudaFuncAttributeMaxDynamicSharedMemorySize, MOE256_SMEM);
    cudaFuncSetAttribute(moe_gemm256<false,false>, cudaFuncAttributeMaxDynamicSharedMemorySize, MOE256_SMEM);

    // ---- weight prep: streaming converts ----
    long nproj4 = (long)CD*CD/4;
    convert_kernel<true ><<<1024, 256>>>(Wq, p_wqh, p_wql, nproj4, WSCALE);
    convert_kernel<true ><<<1024, 256>>>(Wk, p_wkh, p_wkl, nproj4, WSCALE);
    convert_kernel<true ><<<1024, 256>>>(Wv, p_wvh, p_wvl, nproj4, WSCALE);
    convert_kernel<true ><<<1024, 256>>>(Wo, p_woh, p_wol, nproj4, WSCALE);
    long nff4 = (long)CE*CD*CDFF/4;
    convert_kernel<false><<<8192, 256>>>(ew1, p_w1h, nullptr, nff4, 1.0f);
    convert_kernel<false><<<8192, 256>>>(ew2, p_w2h, nullptr, nff4, 1.0f);

    // 1. RMSNorm 0 -> split fp16
    rmsnorm_kernel<1><<<CBN, 256>>>(hid, ln0, nullptr, p_nh, p_nl);

    // 2. Q/K/V projections -> split fp16 q/k/v directly
    dim3 gproj(CD/128, CBN/128, 1);
    mma_gemm<3,false,false,2><<<gproj, 256>>>(p_nh, p_nl, p_wqh, p_wql, nullptr, p_qh, p_ql, CD, CD, WISCALE, 0, 0, 0);
    mma_gemm<3,false,false,2><<<gproj, 256>>>(p_nh, p_nl, p_wkh, p_wkl, nullptr, p_kh, p_kl, CD, CD, WISCALE, 0, 0, 0);
    mma_gemm<3,false,false,2><<<gproj, 256>>>(p_nh, p_nl, p_wvh, p_wvl, nullptr, p_vh, p_vl, CD, CD, WISCALE, 0, 0, 0);

    // 3. tensor-core attention -> split fp16 ao
    tc_attn<<<dim3(CN/128, CB*CH), 256, TCATTN_SMEM>>>(mask);

    // 4. output projection + residual -> h (fp32)
    mma_gemm<3,false,true,0><<<gproj, 256>>>(p_aoh, p_aol, p_woh, p_wol, hid, p_h, nullptr, CD, CD, WISCALE, 0, 0, 0);

    // 5. RMSNorm 1 -> fp32
    rmsnorm_kernel<0><<<CBN, 256>>>(p_h, ln1, p_n2, nullptr, nullptr);

    // 6. gating (fp32: routing bit-exact)
    logits_kernel<<<CBN/16, 256>>>(gw);
    gate_kernel<<<(CBN + 255)/256, 256>>>();
    routeinit_kernel<<<(CEC + 255)/256, 256>>>();
    capacity_kernel<<<CB, 32>>>();

    // 7. dispatch (fp16)
    gather_h_kernel<<<CEC, CD/4>>>();

    // 8. expert FFN: 256x128 tiles, 64x64 per warp (bit-identical accumulation order)
    moe_gemm256<true,true><<<dim3(CDFF/128, CMZ/256, CE), 256, MOE256_SMEM>>>(
        p_xinh, p_w1h, p_midh, CDFF, CD,
        (long)CMZ*CD, (long)CD*CDFF, (long)CMZ*CDFF);
    moe_gemm256<false,false><<<dim3(CD/128, CMZ/256, CE), 256, MOE256_SMEM>>>(
        p_midh, p_w2h, p_xo, CD, CDFF,
        (long)CMZ*CDFF, (long)CDFF*CD, (long)CMZ*CD);

    // 9. combine + residual 2
    combine_kernel<<<CBN, CD/4>>>(out);

    // 10. aux loss
    loss_kernel<<<1, 128>>>(out, out_size);
}

// round 14
// speedup vs baseline: 1.1666x; 1.1666x over previous
#include <cuda_runtime.h>
#include <cuda_fp16.h>
#include <cstdint>

// ---------------- problem constants ----------------
#define CB   8
#define CN   1024
#define CD   768
#define CH   12
#define CDKV 64
#define CDFF 3072
#define CE   16
#define CCAP 128
#define CBN  (CB*CN)          // 8192 tokens
#define CEC  (CE*CB*CCAP)     // 16384 expert slots
#define CMZ  (CB*CCAP)        // 1024 rows per expert
#define WSCALE 32.0f
#define WISCALE (1.0f/32.0f)

// ---------------- device scratch ----------------
static __device__ float g_h      [CBN*CD];
static __device__ float g_n2     [CBN*CD];
static __device__ float g_raw    [CBN*CE];
static __device__ int   g_e1[CBN], g_e2[CBN], g_s1[CBN], g_s2[CBN];
static __device__ float g_g1[CBN], g_g2[CBN];
static __device__ int   g_cnt1[CB*CE];
static __device__ int   g_route[CEC];
static __device__ float g_xo [CEC*CD];
// split-fp16 activations
static __device__ __half g_nh [CBN*CD], g_nl [CBN*CD];     // normed hi/lo
static __device__ __half g_qh [CBN*CD], g_ql [CBN*CD];     // q hi/lo
static __device__ __half g_kh [CBN*CD], g_kl [CBN*CD];     // k hi/lo
static __device__ __half g_vh [CBN*CD], g_vl [CBN*CD];     // v hi/lo
static __device__ __half g_aoh[CBN*CD], g_aol[CBN*CD];     // attn out hi/lo
// fp16 projection weights, native [K][N], scaled by WSCALE, split hi/lo
static __device__ __half g_wqh[CD*CD], g_wql[CD*CD];
static __device__ __half g_wkh[CD*CD], g_wkl[CD*CD];
static __device__ __half g_wvh[CD*CD], g_wvl[CD*CD];
static __device__ __half g_woh[CD*CD], g_wol[CD*CD];
// fp16 MoE path (weights native [K][N])
static __device__ __half g_xinh[CEC*CD];
static __device__ __half g_midh[CEC*CDFF];
static __device__ __half g_w1h [CE*CD*CDFF];   // [e][D][DFF]
static __device__ __half g_w2h [CE*CDFF*CD];   // [e][DFF][D]

// ================= portable PTX helpers =================
__device__ __forceinline__ uint32_t smem_u32(const void* p) {
    uint32_t a;
    asm("{ .reg .u64 t; cvta.to.shared.u64 t, %1; cvt.u32.u64 %0, t; }" : "=r"(a) : "l"(p));
    return a;
}
#define CP16(dst, src) \
    asm volatile("cp.async.cg.shared.global [%0], [%1], 16;" :: "r"(dst), "l"(src) : "memory")
#define CPCOMMIT() asm volatile("cp.async.commit_group;" ::: "memory")
#define CPWAIT0()  asm volatile("cp.async.wait_group 0;" ::: "memory")
#define LDSM4(r0, r1, r2, r3, addr) \
    asm volatile("ldmatrix.sync.aligned.m8n8.x4.shared.b16 {%0,%1,%2,%3}, [%4];" \
        : "=r"(r0), "=r"(r1), "=r"(r2), "=r"(r3) : "r"(addr))
#define LDSM4T(r0, r1, r2, r3, addr) \
    asm volatile("ldmatrix.sync.aligned.m8n8.x4.trans.shared.b16 {%0,%1,%2,%3}, [%4];" \
        : "=r"(r0), "=r"(r1), "=r"(r2), "=r"(r3) : "r"(addr))
#define MMAH(c, a, b0v, b1v) \
    asm volatile("mma.sync.aligned.m16n8k16.row.col.f32.f16.f16.f32 " \
        "{%0,%1,%2,%3}, {%4,%5,%6,%7}, {%8,%9}, {%0,%1,%2,%3};" \
        : "+f"((c)[0]), "+f"((c)[1]), "+f"((c)[2]), "+f"((c)[3]) \
        : "r"((a)[0]), "r"((a)[1]), "r"((a)[2]), "r"((a)[3]), "r"(b0v), "r"(b1v))

// FMA-pipe exp (no MUFU): magic-number round + degree-6 2^f Taylor + exponent add.
__device__ __forceinline__ float fast_exp(float x) {
    x = fmaxf(x, -80.f);
    float t  = x * 1.44269504f;
    float tt = t + 12582912.f;
    int   ei = __float_as_int(tt) - 0x4B400000;
    float n  = tt - 12582912.f;
    float f  = t - n;
    float u  = f * 0.69314718f;
    float p  = 1.f + u*(1.f + u*(0.5f + u*(0.16666667f + u*(0.041666668f +
               u*(0.0083333338f + u*0.0013888889f)))));
    return __int_as_float(__float_as_int(p) + (ei << 23));
}

// ---------------- RMSNorm (T5, eps=1e-6); OUTMODE 0=fp32, 1=split fp16 ----------------
template<int OUTMODE>
__global__ void rmsnorm_kernel(const float* __restrict__ x,
                               const float* __restrict__ w,
                               float* __restrict__ y,
                               __half* __restrict__ yh,
                               __half* __restrict__ yl) {
    int row = blockIdx.x;
    const float* xr = x + (size_t)row * CD;
    float s = 0.f;
    for (int i = threadIdx.x; i < CD; i += 256) { float v = xr[i]; s = fmaf(v, v, s); }
    for (int o = 16; o; o >>= 1) s += __shfl_xor_sync(0xffffffffu, s, o);
    __shared__ float red[8];
    __shared__ float invs;
    if ((threadIdx.x & 31) == 0) red[threadIdx.x >> 5] = s;
    __syncthreads();
    if (threadIdx.x == 0) {
        float tot = 0.f;
        #pragma unroll
        for (int i = 0; i < 8; i++) tot += red[i];
        invs = rsqrtf(tot / CD + 1e-6f);
    }
    __syncthreads();
    float inv = invs;
    for (int i = threadIdx.x; i < CD; i += 256) {
        float v = xr[i] * inv * w[i];
        if (OUTMODE == 0) {
            y[(size_t)row*CD + i] = v;
        } else {
            __half hv = __float2half_rn(v);
            yh[(size_t)row*CD + i] = hv;
            yl[(size_t)row*CD + i] = __float2half_rn(v - __half2float(hv));
        }
    }
}

// ---------------- unified fp16 tensor-core GEMM (2-stage, static smem) ----------------
template<int TERMS, bool RELU, bool RESID, int OUTM>
__global__ __launch_bounds__(256) void mma_gemm(
    const __half* __restrict__ Ahi, const __half* __restrict__ Alo,
    const __half* __restrict__ Bhi, const __half* __restrict__ Blo,
    const float* __restrict__ Rz, void* __restrict__ Cout, void* __restrict__ Cout2,
    int Nn, int K, float scale, long zA, long zB, long zC)
{
    constexpr int BK    = (TERMS == 3) ? 16 : 32;
    constexpr int NA    = (TERMS == 3) ? 2 : 1;
    constexpr int LDSA  = BK + 8;
    constexpr int LDSB  = 136;
    constexpr uint32_t ATILEB = 128u * LDSA * 2;
    constexpr uint32_t BTILEB = (uint32_t)BK * LDSB * 2;
    constexpr uint32_t STAGEB = NA * (ATILEB + BTILEB);
    constexpr int ACH = 128 * (BK / 8);
    constexpr int BCH = BK * 16;
    constexpr int CPT = NA * (ACH + BCH) / 256;
    __shared__ __align__(16) unsigned char sm[2 * STAGEB];

    long e = blockIdx.z;
    int m0 = blockIdx.y * 128, n0 = blockIdx.x * 128;

    int tid = threadIdx.x, lane = tid & 31, wid = tid >> 5;
    int warp_row = (wid & 3) * 32, warp_col = (wid >> 2) * 64;
    uint32_t sb = smem_u32(sm);

    const __half* cur[CPT];
    long gstep[CPT];
    uint32_t sd[CPT];
    #pragma unroll
    for (int j = 0; j < CPT; j++) {
        int c = tid + j * 256;
        if (c < NA * ACH) {
            int tile = c / ACH;
            int rr = (c % ACH) / (BK / 8);
            int c8 = c % (BK / 8);
            sd[j] = tile * (ATILEB + BTILEB) + (uint32_t)(rr * LDSA + c8 * 8) * 2;
            const __half* src = (tile == 0 ? Ahi : Alo);
            cur[j] = src + e * zA + (long)(m0 + rr) * K + c8 * 8;
            gstep[j] = BK;
        } else {
            int c2 = c - NA * ACH;
            int tile = c2 / BCH;
            int rr = (c2 % BCH) / 16;
            int c8 = c2 % 16;
            sd[j] = tile * (ATILEB + BTILEB) + ATILEB + (uint32_t)(rr * LDSB + c8 * 8) * 2;
            const __half* src = (tile == 0 ? Bhi : Blo);
            cur[j] = src + e * zB + (long)rr * Nn + n0 + c8 * 8;
            gstep[j] = (long)BK * Nn;
        }
    }

    int nk = K / BK;
    #pragma unroll
    for (int j = 0; j < CPT; j++) { CP16(sb + sd[j], cur[j]); cur[j] += gstep[j]; }
    CPCOMMIT();

    float acc[2][8][4];
    #pragma unroll
    for (int mi = 0; mi < 2; mi++)
        #pragma unroll
        for (int ni = 0; ni < 8; ni++)
            #pragma unroll
            for (int j = 0; j < 4; j++) acc[mi][ni][j] = 0.f;

    int lm_r = lane & 15, lm_k = (lane >> 4) << 3;

    for (int kc = 0; kc < nk; kc++) {
        CPWAIT0();
        __syncthreads();
        if (kc + 1 < nk) {
            uint32_t s2 = (uint32_t)((kc + 1) & 1) * STAGEB;
            #pragma unroll
            for (int j = 0; j < CPT; j++) { CP16(sb + s2 + sd[j], cur[j]); cur[j] += gstep[j]; }
            CPCOMMIT();
        }
        uint32_t st = sb + (uint32_t)(kc & 1) * STAGEB;
        #pragma unroll
        for (int k16 = 0; k16 < BK; k16 += 16) {
            uint32_t afh[2][4], afl[2][4];
            #pragma unroll
            for (int mi = 0; mi < 2; mi++) {
                int row = warp_row + mi*16 + lm_r;
                LDSM4(afh[mi][0], afh[mi][1], afh[mi][2], afh[mi][3],
                      st + (uint32_t)(row*LDSA + k16 + lm_k) * 2);
                if (TERMS == 3)
                    LDSM4(afl[mi][0], afl[mi][1], afl[mi][2], afl[mi][3],
                          st + (ATILEB + BTILEB) + (uint32_t)(row*LDSA + k16 + lm_k) * 2);
            }
            #pragma unroll
            for (int nt = 0; nt < 4; nt++) {
                uint32_t boff = (uint32_t)((k16 + lm_r) * LDSB + warp_col + nt*16 + lm_k) * 2;
                uint32_t bh[4], bl[4];
                LDSM4T(bh[0], bh[1], bh[2], bh[3], st + ATILEB + boff);
                if (TERMS == 3)
                    LDSM4T(bl[0], bl[1], bl[2], bl[3],
                           st + (ATILEB + BTILEB) + ATILEB + boff);
                #pragma unroll
                for (int mi = 0; mi < 2; mi++)
                    #pragma unroll
                    for (int hh = 0; hh < 2; hh++) {
                        float* cc = acc[mi][nt*2 + hh];
                        MMAH(cc, afh[mi], bh[2*hh], bh[2*hh + 1]);
                        if (TERMS == 3) {
                            MMAH(cc, afh[mi], bl[2*hh], bl[2*hh + 1]);
                            MMAH(cc, afl[mi], bh[2*hh], bh[2*hh + 1]);
                        }
                    }
            }
        }
    }

    int eg = lane >> 2, et = lane & 3;
    #pragma unroll
    for (int mi = 0; mi < 2; mi++) {
        #pragma unroll
        for (int ni = 0; ni < 8; ni++) {
            long r  = m0 + warp_row + mi*16 + eg;
            long cc = n0 + warp_col + ni*8 + et*2;
            float v0 = acc[mi][ni][0]*scale, v1 = acc[mi][ni][1]*scale;
            float v2 = acc[mi][ni][2]*scale, v3 = acc[mi][ni][3]*scale;
            if (RESID) {
                float2 r0 = *(const float2*)(Rz + r*Nn + cc);
                float2 r1 = *(const float2*)(Rz + (r+8)*Nn + cc);
                v0 += r0.x; v1 += r0.y; v2 += r1.x; v3 += r1.y;
            }
            if (RELU) {
                v0 = fmaxf(v0, 0.f); v1 = fmaxf(v1, 0.f);
                v2 = fmaxf(v2, 0.f); v3 = fmaxf(v3, 0.f);
            }
            if (OUTM == 0) {
                float* C = (float*)Cout + e*zC;
                *(float2*)(C + r*Nn + cc)     = make_float2(v0, v1);
                *(float2*)(C + (r+8)*Nn + cc) = make_float2(v2, v3);
            } else if (OUTM == 1) {
                __half* C = (__half*)Cout + e*zC;
                *(__half2*)(C + r*Nn + cc)     = __floats2half2_rn(v0, v1);
                *(__half2*)(C + (r+8)*Nn + cc) = __floats2half2_rn(v2, v3);
            } else {
                __half* C  = (__half*)Cout  + e*zC;
                __half* C2 = (__half*)Cout2 + e*zC;
                __half2 h0 = __floats2half2_rn(v0, v1);
                float2 f0 = __half22float2(h0);
                *(__half2*)(C  + r*Nn + cc) = h0;
                *(__half2*)(C2 + r*Nn + cc) = __floats2half2_rn(v0 - f0.x, v1 - f0.y);
                __half2 h1 = __floats2half2_rn(v2, v3);
                float2 f1 = __half22float2(h1);
                *(__half2*)(C  + (r+8)*Nn + cc) = h1;
                *(__half2*)(C2 + (r+8)*Nn + cc) = __floats2half2_rn(v2 - f1.x, v3 - f1.y);
            }
        }
    }
}

// ---------------- tensor-core flash attention (split-fp16 3-term, FMA-pipe exp) ----------------
__global__ __launch_bounds__(256) void tc_attn(const int* __restrict__ mask) {
    extern __shared__ __align__(16) unsigned char sm[];
    constexpr uint32_t LDQ = 72;
    constexpr uint32_t QT  = 128*LDQ*2;
    constexpr uint32_t KVT = 64*LDQ*2;
    constexpr uint32_t KVS = 4*KVT;
    constexpr uint32_t KVB = 2*QT;
    constexpr uint32_t MBB = KVB + 2*KVS;

    int tid = threadIdx.x, lane = tid & 31, w = tid >> 5;
    int g = lane >> 2, t4 = lane & 3;
    int lm_r = lane & 15, lm_k = (lane >> 4) << 3;
    int bh = blockIdx.y, b = bh / CH, hh = bh % CH;
    int q0 = blockIdx.x * 128;
    uint32_t sb = smem_u32(sm);
    float* MBf = (float*)(sm + MBB);

    for (int i = tid; i < CN; i += 256)
        MBf[i] = (mask[b*CN + i] != 0) ? 0.f : -1e9f;

    #pragma unroll
    for (int j = 0; j < 8; j++) {
        int c = tid + j*256;
        int arr = c >> 10, idx = c & 1023;
        int row = idx >> 3, ch = idx & 7;
        const __half* src = (arr ? g_ql : g_qh) + ((size_t)(b*CN + q0 + row)*CH + hh)*CDKV + ch*8;
        CP16(sb + (uint32_t)arr*QT + (uint32_t)(row*LDQ + ch*8)*2, src);
    }
    #pragma unroll
    for (int j = 0; j < 8; j++) {
        int c = tid + j*256;
        int arr = c >> 9, idx = c & 511;
        int row = idx >> 3, ch = idx & 7;
        const __half* src = (arr==0 ? g_kh : arr==1 ? g_kl : arr==2 ? g_vh : g_vl)
                          + ((size_t)(b*CN + row)*CH + hh)*CDKV + ch*8;
        CP16(sb + KVB + (uint32_t)arr*KVT + (uint32_t)(row*LDQ + ch*8)*2, src);
    }
    CPCOMMIT();
    CPWAIT0();
    __syncthreads();

    uint32_t qfh[4][4], qfl[4][4];
    #pragma unroll
    for (int kc = 0; kc < 4; kc++) {
        uint32_t a = sb + (uint32_t)((w*16 + lm_r)*LDQ + kc*16 + lm_k)*2;
        LDSM4(qfh[kc][0], qfh[kc][1], qfh[kc][2], qfh[kc][3], a);
        LDSM4(qfl[kc][0], qfl[kc][1], qfl[kc][2], qfl[kc][3], a + QT);
    }

    float m_lo = -1e30f, m_hi = -1e30f, l_lo = 0.f, l_hi = 0.f;
    float o[8][4];
    #pragma unroll
    for (int nd = 0; nd < 8; nd++)
        #pragma unroll
        for (int j = 0; j < 4; j++) o[nd][j] = 0.f;

    for (int kt = 0; kt < 16; kt++) {
        if (kt > 0) { CPWAIT0(); __syncthreads(); }
        if (kt + 1 < 16) {
            uint32_t s2 = (uint32_t)((kt+1) & 1) * KVS;
            #pragma unroll
            for (int j = 0; j < 8; j++) {
                int c = tid + j*256;
                int arr = c >> 9, idx = c & 511;
                int row = idx >> 3, ch = idx & 7;
                const __half* src = (arr==0 ? g_kh : arr==1 ? g_kl : arr==2 ? g_vh : g_vl)
                                  + ((size_t)(b*CN + (kt+1)*64 + row)*CH + hh)*CDKV + ch*8;
                CP16(sb + KVB + s2 + (uint32_t)arr*KVT + (uint32_t)(row*LDQ + ch*8)*2, src);
            }
            CPCOMMIT();
        }
        uint32_t kb = sb + KVB + (uint32_t)(kt & 1) * KVS;

        float cs[8][4];
        #pragma unroll
        for (int ni = 0; ni < 8; ni++)
            #pragma unroll
            for (int j = 0; j < 4; j++) cs[ni][j] = 0.f;
        #pragma unroll
        for (int kc = 0; kc < 4; kc++) {
            #pragma unroll
            for (int nt = 0; nt < 4; nt++) {
                uint32_t ka = kb + (uint32_t)((nt*16 + lm_r)*LDQ + kc*16 + lm_k)*2;
                uint32_t kfh[4], kfl[4];
                LDSM4(kfh[0], kfh[1], kfh[2], kfh[3], ka);
                LDSM4(kfl[0], kfl[1], kfl[2], kfl[3], ka + KVT);
                #pragma unroll
                for (int hx = 0; hx < 2; hx++) {
                    float* cc = cs[nt*2 + hx];
                    MMAH(cc, qfh[kc], kfh[hx], kfh[2+hx]);
                    MMAH(cc, qfh[kc], kfl[hx], kfl[2+hx]);
                    MMAH(cc, qfl[kc], kfh[hx], kfh[2+hx]);
                }
            }
        }
        float tl = -1e30f, th = -1e30f;
        #pragma unroll
        for (int ni = 0; ni < 8; ni++) {
            float b0 = MBf[kt*64 + ni*8 + 2*t4];
            float b1 = MBf[kt*64 + ni*8 + 2*t4 + 1];
            cs[ni][0] += b0; cs[ni][1] += b1; cs[ni][2] += b0; cs[ni][3] += b1;
            tl = fmaxf(tl, fmaxf(cs[ni][0], cs[ni][1]));
            th = fmaxf(th, fmaxf(cs[ni][2], cs[ni][3]));
        }
        tl = fmaxf(tl, __shfl_xor_sync(0xffffffffu, tl, 1));
        tl = fmaxf(tl, __shfl_xor_sync(0xffffffffu, tl, 2));
        th = fmaxf(th, __shfl_xor_sync(0xffffffffu, th, 1));
        th = fmaxf(th, __shfl_xor_sync(0xffffffffu, th, 2));
        float mn_lo = fmaxf(m_lo, tl), mn_hi = fmaxf(m_hi, th);
        float sc_lo = fast_exp(m_lo - mn_lo), sc_hi = fast_exp(m_hi - mn_hi);
        m_lo = mn_lo; m_hi = mn_hi;
        l_lo *= sc_lo; l_hi *= sc_hi;
        #pragma unroll
        for (int nd = 0; nd < 8; nd++) {
            o[nd][0] *= sc_lo; o[nd][1] *= sc_lo;
            o[nd][2] *= sc_hi; o[nd][3] *= sc_hi;
        }
        uint32_t pfh[4][4], pfl[4][4];
        #pragma unroll
        for (int j = 0; j < 4; j++) {
            float a0 = fast_exp(cs[2*j][0] - mn_lo),   a1 = fast_exp(cs[2*j][1] - mn_lo);
            float a2 = fast_exp(cs[2*j][2] - mn_hi),   a3 = fast_exp(cs[2*j][3] - mn_hi);
            float b0 = fast_exp(cs[2*j+1][0] - mn_lo), b1 = fast_exp(cs[2*j+1][1] - mn_lo);
            float b2 = fast_exp(cs[2*j+1][2] - mn_hi), b3 = fast_exp(cs[2*j+1][3] - mn_hi);
            l_lo += (a0 + a1) + (b0 + b1);
            l_hi += (a2 + a3) + (b2 + b3);
            __half2 h; float2 f;
            h = __floats2half2_rn(a0, a1); f = __half22float2(h);
            pfh[j][0] = *(uint32_t*)&h;
            { __half2 lo2 = __floats2half2_rn(a0 - f.x, a1 - f.y); pfl[j][0] = *(uint32_t*)&lo2; }
            h = __floats2half2_rn(a2, a3); f = __half22float2(h);
            pfh[j][1] = *(uint32_t*)&h;
            { __half2 lo2 = __floats2half2_rn(a2 - f.x, a3 - f.y); pfl[j][1] = *(uint32_t*)&lo2; }
            h = __floats2half2_rn(b0, b1); f = __half22float2(h);
            pfh[j][2] = *(uint32_t*)&h;
            { __half2 lo2 = __floats2half2_rn(b0 - f.x, b1 - f.y); pfl[j][2] = *(uint32_t*)&lo2; }
            h = __floats2half2_rn(b2, b3); f = __half22float2(h);
            pfh[j][3] = *(uint32_t*)&h;
            { __half2 lo2 = __floats2half2_rn(b2 - f.x, b3 - f.y); pfl[j][3] = *(uint32_t*)&lo2; }
        }
        #pragma unroll
        for (int j = 0; j < 4; j++) {
            #pragma unroll
            for (int nt = 0; nt < 4; nt++) {
                uint32_t va = kb + 2*KVT + (uint32_t)((j*16 + lm_r)*LDQ + nt*16 + lm_k)*2;
                uint32_t vfh[4], vfl[4];
                LDSM4T(vfh[0], vfh[1], vfh[2], vfh[3], va);
                LDSM4T(vfl[0], vfl[1], vfl[2], vfl[3], va + KVT);
                #pragma unroll
                for (int hx = 0; hx < 2; hx++) {
                    float* cc = o[nt*2 + hx];
                    MMAH(cc, pfh[j], vfh[2*hx], vfh[2*hx+1]);
                    MMAH(cc, pfh[j], vfl[2*hx], vfl[2*hx+1]);
                    MMAH(cc, pfl[j], vfh[2*hx], vfh[2*hx+1]);
                }
            }
        }
    }

    l_lo += __shfl_xor_sync(0xffffffffu, l_lo, 1);
    l_lo += __shfl_xor_sync(0xffffffffu, l_lo, 2);
    l_hi += __shfl_xor_sync(0xffffffffu, l_hi, 1);
    l_hi += __shfl_xor_sync(0xffffffffu, l_hi, 2);
    float il = 1.f / l_lo, ih = 1.f / l_hi;
    int r_lo = q0 + w*16 + g, r_hi = r_lo + 8;
    #pragma unroll
    for (int nd = 0; nd < 8; nd++) {
        int col = nd*8 + 2*t4;
        size_t o_lo = ((size_t)(b*CN + r_lo)*CH + hh)*CDKV + col;
        size_t o_hi = ((size_t)(b*CN + r_hi)*CH + hh)*CDKV + col;
        float v0 = o[nd][0]*il, v1 = o[nd][1]*il;
        float v2 = o[nd][2]*ih, v3 = o[nd][3]*ih;
        __half2 h0 = __floats2half2_rn(v0, v1);
        float2 f0 = __half22float2(h0);
        *(__half2*)(g_aoh + o_lo) = h0;
        *(__half2*)(g_aol + o_lo) = __floats2half2_rn(v0 - f0.x, v1 - f0.y);
        __half2 h1 = __floats2half2_rn(v2, v3);
        float2 f1 = __half22float2(h1);
        *(__half2*)(g_aoh + o_hi) = h1;
        *(__half2*)(g_aol + o_hi) = __floats2half2_rn(v2 - f1.x, v3 - f1.y);
    }
}
#define TCATTN_SMEM (2*(128*72*2) + 2*4*(64*72*2) + 1024*4)

// ---------------- fused gate: logits (fp32, identical loop) + softmax + top2 ----------------
// 16 threads per token; shuffles with width=16. Argmax/top2 exact (same compare
// semantics as the sequential loops: strict >, ties -> lowest index).
__global__ void gate_fused_kernel(const float* __restrict__ gw) {
    int tid = threadIdx.x;
    int tok = blockIdx.x * 16 + (tid >> 4);
    int e = tid & 15;
    const float* xr = g_n2 + (size_t)tok * CD;
    float acc = 0.f;
    #pragma unroll 8
    for (int d = 0; d < CD; d++) acc = fmaf(xr[d], gw[d*CE + e], acc);
    // softmax over the 16 lanes of this token
    float mx = acc;
    #pragma unroll
    for (int o = 8; o; o >>= 1) mx = fmaxf(mx, __shfl_xor_sync(0xffffffffu, mx, o, 16));
    float ex = __expf(acc - mx);
    float sum = ex;
    #pragma unroll
    for (int o = 8; o; o >>= 1) sum += __shfl_xor_sync(0xffffffffu, sum, o, 16);
    float raw = ex / sum;
    g_raw[(size_t)tok*CE + e] = raw;
    // top1: strict >, ties -> lowest index
    float v1 = raw; int i1 = e;
    #pragma unroll
    for (int o = 8; o; o >>= 1) {
        float ov = __shfl_xor_sync(0xffffffffu, v1, o, 16);
        int   oi = __shfl_xor_sync(0xffffffffu, i1, o, 16);
        if (ov > v1 || (ov == v1 && oi < i1)) { v1 = ov; i1 = oi; }
    }
    // top2: exclude i1
    float v2 = (e == i1) ? -1.f : raw; int i2 = e;
    #pragma unroll
    for (int o = 8; o; o >>= 1) {
        float ov = __shfl_xor_sync(0xffffffffu, v2, o, 16);
        int   oi = __shfl_xor_sync(0xffffffffu, i2, o, 16);
        if (ov > v2 || (ov == v2 && oi < i2)) { v2 = ov; i2 = oi; }
    }
    if (e == 0) {
        float denom = v1 + v2 + 1e-9f;
        g_e1[tok] = i1; g_e2[tok] = i2;
        g_g1[tok] = v1 / denom; g_g2[tok] = v2 / denom;
    }
}

// ---------------- capacity assignment: warp-ballot prefix scan per (b,e) ----------------
// 128 warps, one per (b,e). Token-order positions identical to the sequential scan.
// Also -1-fills each warp's unused route slots (replaces routeinit).
__global__ void capacity_scan_kernel() {
    int w = (blockIdx.x * blockDim.x + threadIdx.x) >> 5;   // 0..127
    int lane = threadIdx.x & 31;
    int b = w >> 4, e = w & 15;
    unsigned lmlt = (1u << lane) - 1u;
    int base = (e*CB + b)*CCAP;

    int cnt = 0;
    for (int c = 0; c < CN/32; c++) {
        int t = b*CN + c*32 + lane;
        bool m = (g_e1[t] == e);
        unsigned bal = __ballot_sync(0xffffffffu, m);
        int pos = cnt + __popc(bal & lmlt);
        if (m) {
            if (pos < CCAP) { g_s1[t] = pos; g_route[base + pos] = t; }
            else            { g_s1[t] = -1; g_g1[t] = 0.f; }
        }
        cnt += __popc(bal);
    }
    if (lane == 0) g_cnt1[b*CE + e] = cnt;
    int m1c = cnt < CCAP ? cnt : CCAP;

    int cnt2 = 0;
    for (int c = 0; c < CN/32; c++) {
        int t = b*CN + c*32 + lane;
        bool m = (g_e2[t] == e);
        unsigned bal = __ballot_sync(0xffffffffu, m);
        int pos = m1c + cnt2 + __popc(bal & lmlt);
        if (m) {
            if (pos < CCAP) { g_s2[t] = pos; g_route[base + pos] = t; }
            else            { g_s2[t] = -1; g_g2[t] = 0.f; }
        }
        cnt2 += __popc(bal);
    }
    int fend = m1c + cnt2; if (fend > CCAP) fend = CCAP;
    for (int i = fend + lane; i < CCAP; i += 32) g_route[base + i] = -1;
}

// ---------------- gather tokens into expert slots (fp16 out) ----------------
__global__ void gather_h_kernel() {
    int row = blockIdx.x;
    int t = g_route[row];
    __half2* dst = (__half2*)(g_xinh + (size_t)row * CD);
    int i = threadIdx.x;
    if (t < 0) {
        __half2 z = __floats2half2_rn(0.f, 0.f);
        dst[2*i] = z; dst[2*i+1] = z;
    } else {
        float4 v = ((const float4*)(g_n2 + (size_t)t * CD))[i];
        dst[2*i]   = __floats2half2_rn(v.x, v.y);
        dst[2*i+1] = __floats2half2_rn(v.z, v.w);
    }
}

// ---------------- streaming fp32 -> fp16 convert ----------------
template<bool SPLIT>
__global__ void convert_kernel(const float* __restrict__ in,
                               __half* __restrict__ hi,
                               __half* __restrict__ lo,
                               long n4, float scale) {
    long i = (long)blockIdx.x * blockDim.x + threadIdx.x;
    long stride = (long)gridDim.x * blockDim.x;
    for (; i < n4; i += stride) {
        float4 v = ((const float4*)in)[i];
        v.x *= scale; v.y *= scale; v.z *= scale; v.w *= scale;
        __half2 h0 = __floats2half2_rn(v.x, v.y);
        __half2 h1 = __floats2half2_rn(v.z, v.w);
        ((__half2*)hi)[2*i]   = h0;
        ((__half2*)hi)[2*i+1] = h1;
        if (SPLIT) {
            float2 f0 = __half22float2(h0), f1 = __half22float2(h1);
            ((__half2*)lo)[2*i]   = __floats2half2_rn(v.x - f0.x, v.y - f0.y);
            ((__half2*)lo)[2*i+1] = __floats2half2_rn(v.z - f1.x, v.w - f1.y);
        }
    }
}

// ---------------- 4 projection weight converts in one launch (blockIdx.y selects) ----------------
struct ConvSlots {
    const float* in[4];
    __half* hi[4];
    __half* lo[4];
};
__global__ void convert4_kernel(ConvSlots s) {
    int sl = blockIdx.y;
    const float* in = s.in[sl];
    __half* hi = s.hi[sl];
    __half* lo = s.lo[sl];
    const long n4 = (long)CD*CD/4;
    long i = (long)blockIdx.x * blockDim.x + threadIdx.x;
    long stride = (long)gridDim.x * blockDim.x;
    for (; i < n4; i += stride) {
        float4 v = ((const float4*)in)[i];
        v.x *= WSCALE; v.y *= WSCALE; v.z *= WSCALE; v.w *= WSCALE;
        __half2 h0 = __floats2half2_rn(v.x, v.y);
        __half2 h1 = __floats2half2_rn(v.z, v.w);
        ((__half2*)hi)[2*i]   = h0;
        ((__half2*)hi)[2*i+1] = h1;
        float2 f0 = __half22float2(h0), f1 = __half22float2(h1);
        ((__half2*)lo)[2*i]   = __floats2half2_rn(v.x - f0.x, v.y - f0.y);
        ((__half2*)lo)[2*i+1] = __floats2half2_rn(v.z - f1.x, v.w - f1.y);
    }
}

// ---------------- weighted combine + residual 2 ----------------
__global__ void combine_kernel(float* __restrict__ out) {
    int t = blockIdx.x;
    int b = t / CN;
    const float4* hh = (const float4*)(g_h + (size_t)t * CD);
    float4 v = hh[threadIdx.x];
    int s1 = g_s1[t];
    if (s1 >= 0) {
        float gg = g_g1[t];
        const float4* x1 = (const float4*)(g_xo + ((size_t)(g_e1[t]*CB + b)*CCAP + s1) * CD);
        float4 a = x1[threadIdx.x];
        v.x = fmaf(gg, a.x, v.x); v.y = fmaf(gg, a.y, v.y);
        v.z = fmaf(gg, a.z, v.z); v.w = fmaf(gg, a.w, v.w);
    }
    int s2 = g_s2[t];
    if (s2 >= 0) {
        float gg = g_g2[t];
        const float4* x2 = (const float4*)(g_xo + ((size_t)(g_e2[t]*CB + b)*CCAP + s2) * CD);
        float4 a = x2[threadIdx.x];
        v.x = fmaf(gg, a.x, v.x); v.y = fmaf(gg, a.y, v.y);
        v.z = fmaf(gg, a.z, v.z); v.w = fmaf(gg, a.w, v.w);
    }
    ((float4*)out)[(size_t)t * (CD/4) + threadIdx.x] = v;
}

// ---------------- aux loss ----------------
__global__ void loss_kernel(float* __restrict__ out, int out_size) {
    int tid = threadIdx.x;
    int b = tid >> 4, e = tid & 15;
    float proxy = 0.f;
    for (int n = 0; n < CN; n++) proxy += g_raw[((size_t)(b*CN + n))*CE + e];
    proxy /= (float)CN;
    float dens = (float)g_cnt1[b*CE + e] / (float)CN;
    float v = proxy * dens;
    __shared__ float red[128];
    red[tid] = v;
    __syncthreads();
    for (int s = 64; s; s >>= 1) {
        if (tid < s) red[tid] += red[tid + s];
        __syncthreads();
    }
    if (tid == 0) {
        float loss = red[0] / (float)(CB*CE) * (float)(CE*CE) * 0.01f;
        const int base = CBN*CD;
        if (out_size > base) out[base] = loss;
        for (int i = base + 1; i < out_size; i++) out[i] = 0.f;
    }
}

// ---------------- launcher ----------------
extern "C" void kernel_launch(void* const* d_in, const int* in_sizes, int n_in,
                              void* d_out, int out_size) {
    const float* hid   = (const float*)d_in[0];
    const int*   mask  = (const int*)d_in[1];
    const float* ln0   = (const float*)d_in[2];
    const float* Wq    = (const float*)d_in[3];
    const float* Wk    = (const float*)d_in[4];
    const float* Wv    = (const float*)d_in[5];
    const float* Wo    = (const float*)d_in[6];
    const float* ln1   = (const float*)d_in[7];
    const float* gw    = (const float*)d_in[8];
    const float* ew1   = (const float*)d_in[9];
    const float* ew2   = (const float*)d_in[10];
    float* out = (float*)d_out;

    float *p_h, *p_n2, *p_xo;
    __half *p_nh, *p_nl, *p_qh, *p_ql, *p_kh, *p_kl, *p_vh, *p_vl, *p_aoh, *p_aol;
    __half *p_wqh, *p_wql, *p_wkh, *p_wkl, *p_wvh, *p_wvl, *p_woh, *p_wol;
    __half *p_xinh, *p_midh, *p_w1h, *p_w2h;
    cudaGetSymbolAddress((void**)&p_h,    g_h);
    cudaGetSymbolAddress((void**)&p_n2,   g_n2);
    cudaGetSymbolAddress((void**)&p_xo,   g_xo);
    cudaGetSymbolAddress((void**)&p_nh,   g_nh);
    cudaGetSymbolAddress((void**)&p_nl,   g_nl);
    cudaGetSymbolAddress((void**)&p_qh,   g_qh);
    cudaGetSymbolAddress((void**)&p_ql,   g_ql);
    cudaGetSymbolAddress((void**)&p_kh,   g_kh);
    cudaGetSymbolAddress((void**)&p_kl,   g_kl);
    cudaGetSymbolAddress((void**)&p_vh,   g_vh);
    cudaGetSymbolAddress((void**)&p_vl,   g_vl);
    cudaGetSymbolAddress((void**)&p_aoh,  g_aoh);
    cudaGetSymbolAddress((void**)&p_aol,  g_aol);
    cudaGetSymbolAddress((void**)&p_wqh,  g_wqh);
    cudaGetSymbolAddress((void**)&p_wql,  g_wql);
    cudaGetSymbolAddress((void**)&p_wkh,  g_wkh);
    cudaGetSymbolAddress((void**)&p_wkl,  g_wkl);
    cudaGetSymbolAddress((void**)&p_wvh,  g_wvh);
    cudaGetSymbolAddress((void**)&p_wvl,  g_wvl);
    cudaGetSymbolAddress((void**)&p_woh,  g_woh);
    cudaGetSymbolAddress((void**)&p_wol,  g_wol);
    cudaGetSymbolAddress((void**)&p_xinh, g_xinh);
    cudaGetSymbolAddress((void**)&p_midh, g_midh);
    cudaGetSymbolAddress((void**)&p_w1h,  g_w1h);
    cudaGetSymbolAddress((void**)&p_w2h,  g_w2h);

    cudaFuncSetAttribute(tc_attn, cudaFuncAttributeMaxDynamicSharedMemorySize, TCATTN_SMEM);

    // ---- weight prep: 4 projection converts in one launch + 2 FFN converts ----
    ConvSlots cs;
    cs.in[0] = Wq; cs.hi[0] = p_wqh; cs.lo[0] = p_wql;
    cs.in[1] = Wk; cs.hi[1] = p_wkh; cs.lo[1] = p_wkl;
    cs.in[2] = Wv; cs.hi[2] = p_wvh; cs.lo[2] = p_wvl;
    cs.in[3] = Wo; cs.hi[3] = p_woh; cs.lo[3] = p_wol;
    convert4_kernel<<<dim3(256, 4), 256>>>(cs);
    long nff4 = (long)CE*CD*CDFF/4;
    convert_kernel<false><<<8192, 256>>>(ew1, p_w1h, nullptr, nff4, 1.0f);
    convert_kernel<false><<<8192, 256>>>(ew2, p_w2h, nullptr, nff4, 1.0f);

    // 1. RMSNorm 0 -> split fp16
    rmsnorm_kernel<1><<<CBN, 256>>>(hid, ln0, nullptr, p_nh, p_nl);

    // 2. Q/K/V projections -> split fp16 q/k/v directly
    dim3 gproj(CD/128, CBN/128, 1);
    mma_gemm<3,false,false,2><<<gproj, 256>>>(p_nh, p_nl, p_wqh, p_wql, nullptr, p_qh, p_ql, CD, CD, WISCALE, 0, 0, 0);
    mma_gemm<3,false,false,2><<<gproj, 256>>>(p_nh, p_nl, p_wkh, p_wkl, nullptr, p_kh, p_kl, CD, CD, WISCALE, 0, 0, 0);
    mma_gemm<3,false,false,2><<<gproj, 256>>>(p_nh, p_nl, p_wvh, p_wvl, nullptr, p_vh, p_vl, CD, CD, WISCALE, 0, 0, 0);

    // 3. tensor-core attention -> split fp16 ao
    tc_attn<<<dim3(CN/128, CB*CH), 256, TCATTN_SMEM>>>(mask);

    // 4. output projection + residual -> h (fp32)
    mma_gemm<3,false,true,0><<<gproj, 256>>>(p_aoh, p_aol, p_woh, p_wol, hid, p_h, nullptr, CD, CD, WISCALE, 0, 0, 0);

    // 5. RMSNorm 1 -> fp32
    rmsnorm_kernel<0><<<CBN, 256>>>(p_h, ln1, p_n2, nullptr, nullptr);

    // 6. gating: fused logits+softmax+top2, then warp-scan capacity (incl. route init)
    gate_fused_kernel<<<CBN/16, 256>>>(gw);
    capacity_scan_kernel<<<16, 256>>>();

    // 7. dispatch (fp16)
    gather_h_kernel<<<CEC, CD/4>>>();

    // 8. expert FFN (fp16 mma, fp32 accum; 128x128 tiles — validated best shape)
    mma_gemm<1,true,false,1><<<dim3(CDFF/128, CMZ/128, CE), 256>>>(
        p_xinh, nullptr, p_w1h, nullptr, nullptr, p_midh, nullptr, CDFF, CD, 1.0f,
        (long)CMZ*CD, (long)CD*CDFF, (long)CMZ*CDFF);
    mma_gemm<1,false,false,0><<<dim3(CD/128, CMZ/128, CE), 256>>>(
        p_midh, nullptr, p_w2h, nullptr, nullptr, p_xo, nullptr, CD, CDFF, 1.0f,
        (long)CMZ*CDFF, (long)CDFF*CD, (long)CMZ*CD);

    // 9. combine + residual 2
    combine_kernel<<<CBN, CD/4>>>(out);

    // 10. aux loss
    loss_kernel<<<1, 128>>>(out, out_size);
}

// round 15
// speedup vs baseline: 1.2781x; 1.0956x over previous
#include <cuda_runtime.h>
#include <cuda_fp16.h>
#include <cstdint>

// ---------------- problem constants ----------------
#define CB   8
#define CN   1024
#define CD   768
#define CH   12
#define CDKV 64
#define CDFF 3072
#define CE   16
#define CCAP 128
#define CBN  (CB*CN)          // 8192 tokens
#define CEC  (CE*CB*CCAP)     // 16384 expert slots
#define CMZ  (CB*CCAP)        // 1024 rows per expert
#define QKVS (3*CD)           // 2304: combined qkv row stride
#define WSCALE 32.0f
#define WISCALE (1.0f/32.0f)

// ---------------- device scratch ----------------
static __device__ float g_h      [CBN*CD];
static __device__ float g_n2     [CBN*CD];
static __device__ float g_raw    [CBN*CE];
static __device__ int   g_e1[CBN], g_e2[CBN], g_s1[CBN], g_s2[CBN];
static __device__ float g_g1[CBN], g_g2[CBN];
static __device__ int   g_cnt1[CB*CE];
static __device__ int   g_route[CEC];
static __device__ float g_xo [CEC*CD];
// split-fp16 activations
static __device__ __half g_nh [CBN*CD], g_nl [CBN*CD];       // normed hi/lo
static __device__ __half g_qkvh[CBN*QKVS], g_qkvl[CBN*QKVS]; // combined q|k|v hi/lo
static __device__ __half g_aoh[CBN*CD], g_aol[CBN*CD];       // attn out hi/lo
// fp16 projection weights, native [K][N], scaled by WSCALE, split hi/lo
static __device__ __half g_wqkvh[CD*QKVS], g_wqkvl[CD*QKVS]; // combined Wq|Wk|Wv
static __device__ __half g_woh[CD*CD], g_wol[CD*CD];
// fp16 MoE path (weights native [K][N])
static __device__ __half g_xinh[CEC*CD];
static __device__ __half g_midh[CEC*CDFF];
static __device__ __half g_w1h [CE*CD*CDFF];   // [e][D][DFF]
static __device__ __half g_w2h [CE*CDFF*CD];   // [e][DFF][D]

// ================= portable PTX helpers =================
__device__ __forceinline__ uint32_t smem_u32(const void* p) {
    uint32_t a;
    asm("{ .reg .u64 t; cvta.to.shared.u64 t, %1; cvt.u32.u64 %0, t; }" : "=r"(a) : "l"(p));
    return a;
}
#define CP16(dst, src) \
    asm volatile("cp.async.cg.shared.global [%0], [%1], 16;" :: "r"(dst), "l"(src) : "memory")
#define CPCOMMIT() asm volatile("cp.async.commit_group;" ::: "memory")
#define CPWAIT0()  asm volatile("cp.async.wait_group 0;" ::: "memory")
#define LDSM4(r0, r1, r2, r3, addr) \
    asm volatile("ldmatrix.sync.aligned.m8n8.x4.shared.b16 {%0,%1,%2,%3}, [%4];" \
        : "=r"(r0), "=r"(r1), "=r"(r2), "=r"(r3) : "r"(addr))
#define LDSM4T(r0, r1, r2, r3, addr) \
    asm volatile("ldmatrix.sync.aligned.m8n8.x4.trans.shared.b16 {%0,%1,%2,%3}, [%4];" \
        : "=r"(r0), "=r"(r1), "=r"(r2), "=r"(r3) : "r"(addr))
#define MMAH(c, a, b0v, b1v) \
    asm volatile("mma.sync.aligned.m16n8k16.row.col.f32.f16.f16.f32 " \
        "{%0,%1,%2,%3}, {%4,%5,%6,%7}, {%8,%9}, {%0,%1,%2,%3};" \
        : "+f"((c)[0]), "+f"((c)[1]), "+f"((c)[2]), "+f"((c)[3]) \
        : "r"((a)[0]), "r"((a)[1]), "r"((a)[2]), "r"((a)[3]), "r"(b0v), "r"(b1v))

// FMA-pipe exp (no MUFU): magic-number round + degree-6 2^f Taylor + exponent add.
__device__ __forceinline__ float fast_exp(float x) {
    x = fmaxf(x, -80.f);
    float t  = x * 1.44269504f;
    float tt = t + 12582912.f;
    int   ei = __float_as_int(tt) - 0x4B400000;
    float n  = tt - 12582912.f;
    float f  = t - n;
    float u  = f * 0.69314718f;
    float p  = 1.f + u*(1.f + u*(0.5f + u*(0.16666667f + u*(0.041666668f +
               u*(0.0083333338f + u*0.0013888889f)))));
    return __int_as_float(__float_as_int(p) + (ei << 23));
}

// ---------------- RMSNorm (T5, eps=1e-6); OUTMODE 0=fp32, 1=split fp16 ----------------
template<int OUTMODE>
__global__ void rmsnorm_kernel(const float* __restrict__ x,
                               const float* __restrict__ w,
                               float* __restrict__ y,
                               __half* __restrict__ yh,
                               __half* __restrict__ yl) {
    int row = blockIdx.x;
    const float* xr = x + (size_t)row * CD;
    float s = 0.f;
    for (int i = threadIdx.x; i < CD; i += 256) { float v = xr[i]; s = fmaf(v, v, s); }
    for (int o = 16; o; o >>= 1) s += __shfl_xor_sync(0xffffffffu, s, o);
    __shared__ float red[8];
    __shared__ float invs;
    if ((threadIdx.x & 31) == 0) red[threadIdx.x >> 5] = s;
    __syncthreads();
    if (threadIdx.x == 0) {
        float tot = 0.f;
        #pragma unroll
        for (int i = 0; i < 8; i++) tot += red[i];
        invs = rsqrtf(tot / CD + 1e-6f);
    }
    __syncthreads();
    float inv = invs;
    for (int i = threadIdx.x; i < CD; i += 256) {
        float v = xr[i] * inv * w[i];
        if (OUTMODE == 0) {
            y[(size_t)row*CD + i] = v;
        } else {
            __half hv = __float2half_rn(v);
            yh[(size_t)row*CD + i] = hv;
            yl[(size_t)row*CD + i] = __float2half_rn(v - __half2float(hv));
        }
    }
}

// ---------------- unified fp16 tensor-core GEMM (2-stage, static smem) ----------------
template<int TERMS, bool RELU, bool RESID, int OUTM>
__global__ __launch_bounds__(256) void mma_gemm(
    const __half* __restrict__ Ahi, const __half* __restrict__ Alo,
    const __half* __restrict__ Bhi, const __half* __restrict__ Blo,
    const float* __restrict__ Rz, void* __restrict__ Cout, void* __restrict__ Cout2,
    int Nn, int K, float scale, long zA, long zB, long zC)
{
    constexpr int BK    = (TERMS == 3) ? 16 : 32;
    constexpr int NA    = (TERMS == 3) ? 2 : 1;
    constexpr int LDSA  = BK + 8;
    constexpr int LDSB  = 136;
    constexpr uint32_t ATILEB = 128u * LDSA * 2;
    constexpr uint32_t BTILEB = (uint32_t)BK * LDSB * 2;
    constexpr uint32_t STAGEB = NA * (ATILEB + BTILEB);
    constexpr int ACH = 128 * (BK / 8);
    constexpr int BCH = BK * 16;
    constexpr int CPT = NA * (ACH + BCH) / 256;
    __shared__ __align__(16) unsigned char sm[2 * STAGEB];

    long e = blockIdx.z;
    int m0 = blockIdx.y * 128, n0 = blockIdx.x * 128;

    int tid = threadIdx.x, lane = tid & 31, wid = tid >> 5;
    int warp_row = (wid & 3) * 32, warp_col = (wid >> 2) * 64;
    uint32_t sb = smem_u32(sm);

    const __half* cur[CPT];
    long gstep[CPT];
    uint32_t sd[CPT];
    #pragma unroll
    for (int j = 0; j < CPT; j++) {
        int c = tid + j * 256;
        if (c < NA * ACH) {
            int tile = c / ACH;
            int rr = (c % ACH) / (BK / 8);
            int c8 = c % (BK / 8);
            sd[j] = tile * (ATILEB + BTILEB) + (uint32_t)(rr * LDSA + c8 * 8) * 2;
            const __half* src = (tile == 0 ? Ahi : Alo);
            cur[j] = src + e * zA + (long)(m0 + rr) * K + c8 * 8;
            gstep[j] = BK;
        } else {
            int c2 = c - NA * ACH;
            int tile = c2 / BCH;
            int rr = (c2 % BCH) / 16;
            int c8 = c2 % 16;
            sd[j] = tile * (ATILEB + BTILEB) + ATILEB + (uint32_t)(rr * LDSB + c8 * 8) * 2;
            const __half* src = (tile == 0 ? Bhi : Blo);
            cur[j] = src + e * zB + (long)rr * Nn + n0 + c8 * 8;
            gstep[j] = (long)BK * Nn;
        }
    }

    int nk = K / BK;
    #pragma unroll
    for (int j = 0; j < CPT; j++) { CP16(sb + sd[j], cur[j]); cur[j] += gstep[j]; }
    CPCOMMIT();

    float acc[2][8][4];
    #pragma unroll
    for (int mi = 0; mi < 2; mi++)
        #pragma unroll
        for (int ni = 0; ni < 8; ni++)
            #pragma unroll
            for (int j = 0; j < 4; j++) acc[mi][ni][j] = 0.f;

    int lm_r = lane & 15, lm_k = (lane >> 4) << 3;

    for (int kc = 0; kc < nk; kc++) {
        CPWAIT0();
        __syncthreads();
        if (kc + 1 < nk) {
            uint32_t s2 = (uint32_t)((kc + 1) & 1) * STAGEB;
            #pragma unroll
            for (int j = 0; j < CPT; j++) { CP16(sb + s2 + sd[j], cur[j]); cur[j] += gstep[j]; }
            CPCOMMIT();
        }
        uint32_t st = sb + (uint32_t)(kc & 1) * STAGEB;
        #pragma unroll
        for (int k16 = 0; k16 < BK; k16 += 16) {
            uint32_t afh[2][4], afl[2][4];
            #pragma unroll
            for (int mi = 0; mi < 2; mi++) {
                int row = warp_row + mi*16 + lm_r;
                LDSM4(afh[mi][0], afh[mi][1], afh[mi][2], afh[mi][3],
                      st + (uint32_t)(row*LDSA + k16 + lm_k) * 2);
                if (TERMS == 3)
                    LDSM4(afl[mi][0], afl[mi][1], afl[mi][2], afl[mi][3],
                          st + (ATILEB + BTILEB) + (uint32_t)(row*LDSA + k16 + lm_k) * 2);
            }
            #pragma unroll
            for (int nt = 0; nt < 4; nt++) {
                uint32_t boff = (uint32_t)((k16 + lm_r) * LDSB + warp_col + nt*16 + lm_k) * 2;
                uint32_t bh[4], bl[4];
                LDSM4T(bh[0], bh[1], bh[2], bh[3], st + ATILEB + boff);
                if (TERMS == 3)
                    LDSM4T(bl[0], bl[1], bl[2], bl[3],
                           st + (ATILEB + BTILEB) + ATILEB + boff);
                #pragma unroll
                for (int mi = 0; mi < 2; mi++)
                    #pragma unroll
                    for (int hh = 0; hh < 2; hh++) {
                        float* cc = acc[mi][nt*2 + hh];
                        MMAH(cc, afh[mi], bh[2*hh], bh[2*hh + 1]);
                        if (TERMS == 3) {
                            MMAH(cc, afh[mi], bl[2*hh], bl[2*hh + 1]);
                            MMAH(cc, afl[mi], bh[2*hh], bh[2*hh + 1]);
                        }
                    }
            }
        }
    }

    int eg = lane >> 2, et = lane & 3;
    #pragma unroll
    for (int mi = 0; mi < 2; mi++) {
        #pragma unroll
        for (int ni = 0; ni < 8; ni++) {
            long r  = m0 + warp_row + mi*16 + eg;
            long cc = n0 + warp_col + ni*8 + et*2;
            float v0 = acc[mi][ni][0]*scale, v1 = acc[mi][ni][1]*scale;
            float v2 = acc[mi][ni][2]*scale, v3 = acc[mi][ni][3]*scale;
            if (RESID) {
                float2 r0 = *(const float2*)(Rz + r*Nn + cc);
                float2 r1 = *(const float2*)(Rz + (r+8)*Nn + cc);
                v0 += r0.x; v1 += r0.y; v2 += r1.x; v3 += r1.y;
            }
            if (RELU) {
                v0 = fmaxf(v0, 0.f); v1 = fmaxf(v1, 0.f);
                v2 = fmaxf(v2, 0.f); v3 = fmaxf(v3, 0.f);
            }
            if (OUTM == 0) {
                float* C = (float*)Cout + e*zC;
                *(float2*)(C + r*Nn + cc)     = make_float2(v0, v1);
                *(float2*)(C + (r+8)*Nn + cc) = make_float2(v2, v3);
            } else if (OUTM == 1) {
                __half* C = (__half*)Cout + e*zC;
                *(__half2*)(C + r*Nn + cc)     = __floats2half2_rn(v0, v1);
                *(__half2*)(C + (r+8)*Nn + cc) = __floats2half2_rn(v2, v3);
            } else {
                __half* C  = (__half*)Cout  + e*zC;
                __half* C2 = (__half*)Cout2 + e*zC;
                __half2 h0 = __floats2half2_rn(v0, v1);
                float2 f0 = __half22float2(h0);
                *(__half2*)(C  + r*Nn + cc) = h0;
                *(__half2*)(C2 + r*Nn + cc) = __floats2half2_rn(v0 - f0.x, v1 - f0.y);
                __half2 h1 = __floats2half2_rn(v2, v3);
                float2 f1 = __half22float2(h1);
                *(__half2*)(C  + (r+8)*Nn + cc) = h1;
                *(__half2*)(C2 + (r+8)*Nn + cc) = __floats2half2_rn(v2 - f1.x, v3 - f1.y);
            }
        }
    }
}

// ---------------- tensor-core flash attention (split-fp16 3-term, FMA-pipe exp) ----------------
// Reads q/k/v from the combined [token][2304] split-fp16 buffer (validated in R11).
__global__ __launch_bounds__(256) void tc_attn(const int* __restrict__ mask) {
    extern __shared__ __align__(16) unsigned char sm[];
    constexpr uint32_t LDQ = 72;
    constexpr uint32_t QT  = 128*LDQ*2;
    constexpr uint32_t KVT = 64*LDQ*2;
    constexpr uint32_t KVS = 4*KVT;
    constexpr uint32_t KVB = 2*QT;
    constexpr uint32_t MBB = KVB + 2*KVS;

    int tid = threadIdx.x, lane = tid & 31, w = tid >> 5;
    int g = lane >> 2, t4 = lane & 3;
    int lm_r = lane & 15, lm_k = (lane >> 4) << 3;
    int bh = blockIdx.y, b = bh / CH, hh = bh % CH;
    int q0 = blockIdx.x * 128;
    uint32_t sb = smem_u32(sm);
    float* MBf = (float*)(sm + MBB);

    for (int i = tid; i < CN; i += 256)
        MBf[i] = (mask[b*CN + i] != 0) ? 0.f : -1e9f;

    // prologue: Q(hi+lo) + KV stage 0
    #pragma unroll
    for (int j = 0; j < 8; j++) {
        int c = tid + j*256;
        int arr = c >> 10, idx = c & 1023;
        int row = idx >> 3, ch = idx & 7;
        const __half* src = (arr ? g_qkvl : g_qkvh)
                          + (size_t)(b*CN + q0 + row)*QKVS + hh*CDKV + ch*8;
        CP16(sb + (uint32_t)arr*QT + (uint32_t)(row*LDQ + ch*8)*2, src);
    }
    #pragma unroll
    for (int j = 0; j < 8; j++) {
        int c = tid + j*256;
        int arr = c >> 9, idx = c & 511;
        int row = idx >> 3, ch = idx & 7;
        const __half* bsel = (arr & 1) ? g_qkvl : g_qkvh;
        int part = (arr < 2) ? CD : 2*CD;
        const __half* src = bsel + (size_t)(b*CN + row)*QKVS + part + hh*CDKV + ch*8;
        CP16(sb + KVB + (uint32_t)arr*KVT + (uint32_t)(row*LDQ + ch*8)*2, src);
    }
    CPCOMMIT();
    CPWAIT0();
    __syncthreads();

    uint32_t qfh[4][4], qfl[4][4];
    #pragma unroll
    for (int kc = 0; kc < 4; kc++) {
        uint32_t a = sb + (uint32_t)((w*16 + lm_r)*LDQ + kc*16 + lm_k)*2;
        LDSM4(qfh[kc][0], qfh[kc][1], qfh[kc][2], qfh[kc][3], a);
        LDSM4(qfl[kc][0], qfl[kc][1], qfl[kc][2], qfl[kc][3], a + QT);
    }

    float m_lo = -1e30f, m_hi = -1e30f, l_lo = 0.f, l_hi = 0.f;
    float o[8][4];
    #pragma unroll
    for (int nd = 0; nd < 8; nd++)
        #pragma unroll
        for (int j = 0; j < 4; j++) o[nd][j] = 0.f;

    for (int kt = 0; kt < 16; kt++) {
        if (kt > 0) { CPWAIT0(); __syncthreads(); }
        if (kt + 1 < 16) {
            uint32_t s2 = (uint32_t)((kt+1) & 1) * KVS;
            #pragma unroll
            for (int j = 0; j < 8; j++) {
                int c = tid + j*256;
                int arr = c >> 9, idx = c & 511;
                int row = idx >> 3, ch = idx & 7;
                const __half* bsel = (arr & 1) ? g_qkvl : g_qkvh;
                int part = (arr < 2) ? CD : 2*CD;
                const __half* src = bsel + (size_t)(b*CN + (kt+1)*64 + row)*QKVS + part + hh*CDKV + ch*8;
                CP16(sb + KVB + s2 + (uint32_t)arr*KVT + (uint32_t)(row*LDQ + ch*8)*2, src);
            }
            CPCOMMIT();
        }
        uint32_t kb = sb + KVB + (uint32_t)(kt & 1) * KVS;

        float cs[8][4];
        #pragma unroll
        for (int ni = 0; ni < 8; ni++)
            #pragma unroll
            for (int j = 0; j < 4; j++) cs[ni][j] = 0.f;
        #pragma unroll
        for (int kc = 0; kc < 4; kc++) {
            #pragma unroll
            for (int nt = 0; nt < 4; nt++) {
                uint32_t ka = kb + (uint32_t)((nt*16 + lm_r)*LDQ + kc*16 + lm_k)*2;
                uint32_t kfh[4], kfl[4];
                LDSM4(kfh[0], kfh[1], kfh[2], kfh[3], ka);
                LDSM4(kfl[0], kfl[1], kfl[2], kfl[3], ka + KVT);
                #pragma unroll
                for (int hx = 0; hx < 2; hx++) {
                    float* cc = cs[nt*2 + hx];
                    MMAH(cc, qfh[kc], kfh[hx], kfh[2+hx]);
                    MMAH(cc, qfh[kc], kfl[hx], kfl[2+hx]);
                    MMAH(cc, qfl[kc], kfh[hx], kfh[2+hx]);
                }
            }
        }
        float tl = -1e30f, th = -1e30f;
        #pragma unroll
        for (int ni = 0; ni < 8; ni++) {
            float b0 = MBf[kt*64 + ni*8 + 2*t4];
            float b1 = MBf[kt*64 + ni*8 + 2*t4 + 1];
            cs[ni][0] += b0; cs[ni][1] += b1; cs[ni][2] += b0; cs[ni][3] += b1;
            tl = fmaxf(tl, fmaxf(cs[ni][0], cs[ni][1]));
            th = fmaxf(th, fmaxf(cs[ni][2], cs[ni][3]));
        }
        tl = fmaxf(tl, __shfl_xor_sync(0xffffffffu, tl, 1));
        tl = fmaxf(tl, __shfl_xor_sync(0xffffffffu, tl, 2));
        th = fmaxf(th, __shfl_xor_sync(0xffffffffu, th, 1));
        th = fmaxf(th, __shfl_xor_sync(0xffffffffu, th, 2));
        float mn_lo = fmaxf(m_lo, tl), mn_hi = fmaxf(m_hi, th);
        float sc_lo = fast_exp(m_lo - mn_lo), sc_hi = fast_exp(m_hi - mn_hi);
        m_lo = mn_lo; m_hi = mn_hi;
        l_lo *= sc_lo; l_hi *= sc_hi;
        #pragma unroll
        for (int nd = 0; nd < 8; nd++) {
            o[nd][0] *= sc_lo; o[nd][1] *= sc_lo;
            o[nd][2] *= sc_hi; o[nd][3] *= sc_hi;
        }
        uint32_t pfh[4][4], pfl[4][4];
        #pragma unroll
        for (int j = 0; j < 4; j++) {
            float a0 = fast_exp(cs[2*j][0] - mn_lo),   a1 = fast_exp(cs[2*j][1] - mn_lo);
            float a2 = fast_exp(cs[2*j][2] - mn_hi),   a3 = fast_exp(cs[2*j][3] - mn_hi);
            float b0 = fast_exp(cs[2*j+1][0] - mn_lo), b1 = fast_exp(cs[2*j+1][1] - mn_lo);
            float b2 = fast_exp(cs[2*j+1][2] - mn_hi), b3 = fast_exp(cs[2*j+1][3] - mn_hi);
            l_lo += (a0 + a1) + (b0 + b1);
            l_hi += (a2 + a3) + (b2 + b3);
            __half2 h; float2 f;
            h = __floats2half2_rn(a0, a1); f = __half22float2(h);
            pfh[j][0] = *(uint32_t*)&h;
            { __half2 lo2 = __floats2half2_rn(a0 - f.x, a1 - f.y); pfl[j][0] = *(uint32_t*)&lo2; }
            h = __floats2half2_rn(a2, a3); f = __half22float2(h);
            pfh[j][1] = *(uint32_t*)&h;
            { __half2 lo2 = __floats2half2_rn(a2 - f.x, a3 - f.y); pfl[j][1] = *(uint32_t*)&lo2; }
            h = __floats2half2_rn(b0, b1); f = __half22float2(h);
            pfh[j][2] = *(uint32_t*)&h;
            { __half2 lo2 = __floats2half2_rn(b0 - f.x, b1 - f.y); pfl[j][2] = *(uint32_t*)&lo2; }
            h = __floats2half2_rn(b2, b3); f = __half22float2(h);
            pfh[j][3] = *(uint32_t*)&h;
            { __half2 lo2 = __floats2half2_rn(b2 - f.x, b3 - f.y); pfl[j][3] = *(uint32_t*)&lo2; }
        }
        #pragma unroll
        for (int j = 0; j < 4; j++) {
            #pragma unroll
            for (int nt = 0; nt < 4; nt++) {
                uint32_t va = kb + 2*KVT + (uint32_t)((j*16 + lm_r)*LDQ + nt*16 + lm_k)*2;
                uint32_t vfh[4], vfl[4];
                LDSM4T(vfh[0], vfh[1], vfh[2], vfh[3], va);
                LDSM4T(vfl[0], vfl[1], vfl[2], vfl[3], va + KVT);
                #pragma unroll
                for (int hx = 0; hx < 2; hx++) {
                    float* cc = o[nt*2 + hx];
                    MMAH(cc, pfh[j], vfh[2*hx], vfh[2*hx+1]);
                    MMAH(cc, pfh[j], vfl[2*hx], vfl[2*hx+1]);
                    MMAH(cc, pfl[j], vfh[2*hx], vfh[2*hx+1]);
                }
            }
        }
    }

    l_lo += __shfl_xor_sync(0xffffffffu, l_lo, 1);
    l_lo += __shfl_xor_sync(0xffffffffu, l_lo, 2);
    l_hi += __shfl_xor_sync(0xffffffffu, l_hi, 1);
    l_hi += __shfl_xor_sync(0xffffffffu, l_hi, 2);
    float il = 1.f / l_lo, ih = 1.f / l_hi;
    int r_lo = q0 + w*16 + g, r_hi = r_lo + 8;
    #pragma unroll
    for (int nd = 0; nd < 8; nd++) {
        int col = nd*8 + 2*t4;
        size_t o_lo = ((size_t)(b*CN + r_lo)*CH + hh)*CDKV + col;
        size_t o_hi = ((size_t)(b*CN + r_hi)*CH + hh)*CDKV + col;
        float v0 = o[nd][0]*il, v1 = o[nd][1]*il;
        float v2 = o[nd][2]*ih, v3 = o[nd][3]*ih;
        __half2 h0 = __floats2half2_rn(v0, v1);
        float2 f0 = __half22float2(h0);
        *(__half2*)(g_aoh + o_lo) = h0;
        *(__half2*)(g_aol + o_lo) = __floats2half2_rn(v0 - f0.x, v1 - f0.y);
        __half2 h1 = __floats2half2_rn(v2, v3);
        float2 f1 = __half22float2(h1);
        *(__half2*)(g_aoh + o_hi) = h1;
        *(__half2*)(g_aol + o_hi) = __floats2half2_rn(v2 - f1.x, v3 - f1.y);
    }
}
#define TCATTN_SMEM (2*(128*72*2) + 2*4*(64*72*2) + 1024*4)

// ---------------- fused gate: logits + softmax + top2 (routing-exact) ----------------
__global__ void gate_fused_kernel(const float* __restrict__ gw) {
    int tid = threadIdx.x;
    int tok = blockIdx.x * 16 + (tid >> 4);
    int e = tid & 15;
    const float* xr = g_n2 + (size_t)tok * CD;
    float acc = 0.f;
    #pragma unroll 8
    for (int d = 0; d < CD; d++) acc = fmaf(xr[d], gw[d*CE + e], acc);
    float mx = acc;
    #pragma unroll
    for (int o = 8; o; o >>= 1) mx = fmaxf(mx, __shfl_xor_sync(0xffffffffu, mx, o, 16));
    float ex = __expf(acc - mx);
    float sum = ex;
    #pragma unroll
    for (int o = 8; o; o >>= 1) sum += __shfl_xor_sync(0xffffffffu, sum, o, 16);
    float raw = ex / sum;
    g_raw[(size_t)tok*CE + e] = raw;
    float v1 = raw; int i1 = e;
    #pragma unroll
    for (int o = 8; o; o >>= 1) {
        float ov = __shfl_xor_sync(0xffffffffu, v1, o, 16);
        int   oi = __shfl_xor_sync(0xffffffffu, i1, o, 16);
        if (ov > v1 || (ov == v1 && oi < i1)) { v1 = ov; i1 = oi; }
    }
    float v2 = (e == i1) ? -1.f : raw; int i2 = e;
    #pragma unroll
    for (int o = 8; o; o >>= 1) {
        float ov = __shfl_xor_sync(0xffffffffu, v2, o, 16);
        int   oi = __shfl_xor_sync(0xffffffffu, i2, o, 16);
        if (ov > v2 || (ov == v2 && oi < i2)) { v2 = ov; i2 = oi; }
    }
    if (e == 0) {
        float denom = v1 + v2 + 1e-9f;
        g_e1[tok] = i1; g_e2[tok] = i2;
        g_g1[tok] = v1 / denom; g_g2[tok] = v2 / denom;
    }
}

// ---------------- capacity assignment: warp-ballot prefix scan per (b,e) ----------------
__global__ void capacity_scan_kernel() {
    int w = (blockIdx.x * blockDim.x + threadIdx.x) >> 5;   // 0..127
    int lane = threadIdx.x & 31;
    int b = w >> 4, e = w & 15;
    unsigned lmlt = (1u << lane) - 1u;
    int base = (e*CB + b)*CCAP;

    int cnt = 0;
    for (int c = 0; c < CN/32; c++) {
        int t = b*CN + c*32 + lane;
        bool m = (g_e1[t] == e);
        unsigned bal = __ballot_sync(0xffffffffu, m);
        int pos = cnt + __popc(bal & lmlt);
        if (m) {
            if (pos < CCAP) { g_s1[t] = pos; g_route[base + pos] = t; }
            else            { g_s1[t] = -1; g_g1[t] = 0.f; }
        }
        cnt += __popc(bal);
    }
    if (lane == 0) g_cnt1[b*CE + e] = cnt;
    int m1c = cnt < CCAP ? cnt : CCAP;

    int cnt2 = 0;
    for (int c = 0; c < CN/32; c++) {
        int t = b*CN + c*32 + lane;
        bool m = (g_e2[t] == e);
        unsigned bal = __ballot_sync(0xffffffffu, m);
        int pos = m1c + cnt2 + __popc(bal & lmlt);
        if (m) {
            if (pos < CCAP) { g_s2[t] = pos; g_route[base + pos] = t; }
            else            { g_s2[t] = -1; g_g2[t] = 0.f; }
        }
        cnt2 += __popc(bal);
    }
    int fend = m1c + cnt2; if (fend > CCAP) fend = CCAP;
    for (int i = fend + lane; i < CCAP; i += 32) g_route[base + i] = -1;
}

// ---------------- gather tokens into expert slots (fp16 out) ----------------
__global__ void gather_h_kernel() {
    int row = blockIdx.x;
    int t = g_route[row];
    __half2* dst = (__half2*)(g_xinh + (size_t)row * CD);
    int i = threadIdx.x;
    if (t < 0) {
        __half2 z = __floats2half2_rn(0.f, 0.f);
        dst[2*i] = z; dst[2*i+1] = z;
    } else {
        float4 v = ((const float4*)(g_n2 + (size_t)t * CD))[i];
        dst[2*i]   = __floats2half2_rn(v.x, v.y);
        dst[2*i+1] = __floats2half2_rn(v.z, v.w);
    }
}

// ---------------- streaming fp32 -> fp16 convert ----------------
template<bool SPLIT>
__global__ void convert_kernel(const float* __restrict__ in,
                               __half* __restrict__ hi,
                               __half* __restrict__ lo,
                               long n4, float scale) {
    long i = (long)blockIdx.x * blockDim.x + threadIdx.x;
    long stride = (long)gridDim.x * blockDim.x;
    for (; i < n4; i += stride) {
        float4 v = ((const float4*)in)[i];
        v.x *= scale; v.y *= scale; v.z *= scale; v.w *= scale;
        __half2 h0 = __floats2half2_rn(v.x, v.y);
        __half2 h1 = __floats2half2_rn(v.z, v.w);
        ((__half2*)hi)[2*i]   = h0;
        ((__half2*)hi)[2*i+1] = h1;
        if (SPLIT) {
            float2 f0 = __half22float2(h0), f1 = __half22float2(h1);
            ((__half2*)lo)[2*i]   = __floats2half2_rn(v.x - f0.x, v.y - f0.y);
            ((__half2*)lo)[2*i+1] = __floats2half2_rn(v.z - f1.x, v.w - f1.y);
        }
    }
}

// ---------------- combined QKV weight convert+split into [768][2304] (validated R11) ----------------
__global__ void convert_qkv_kernel(const float* __restrict__ Wq,
                                   const float* __restrict__ Wk,
                                   const float* __restrict__ Wv,
                                   __half* __restrict__ hi,
                                   __half* __restrict__ lo) {
    const long n4 = (long)CD*CD/4;
    long i = (long)blockIdx.x * blockDim.x + threadIdx.x;
    long stride = (long)gridDim.x * blockDim.x;
    for (; i < n4; i += stride) {
        long elem = i * 4;
        long k = elem / CD, n = elem % CD;
        size_t obase = (size_t)k * QKVS + n;
        #pragma unroll
        for (int part = 0; part < 3; part++) {
            const float* W = (part == 0 ? Wq : part == 1 ? Wk : Wv);
            float4 v = ((const float4*)W)[i];
            v.x *= WSCALE; v.y *= WSCALE; v.z *= WSCALE; v.w *= WSCALE;
            __half2 h0 = __floats2half2_rn(v.x, v.y);
            __half2 h1 = __floats2half2_rn(v.z, v.w);
            size_t o = obase + (size_t)part * CD;
            *(__half2*)(hi + o)     = h0;
            *(__half2*)(hi + o + 2) = h1;
            float2 f0 = __half22float2(h0), f1 = __half22float2(h1);
            *(__half2*)(lo + o)     = __floats2half2_rn(v.x - f0.x, v.y - f0.y);
            *(__half2*)(lo + o + 2) = __floats2half2_rn(v.z - f1.x, v.w - f1.y);
        }
    }
}

// ---------------- weighted combine + residual 2 ----------------
__global__ void combine_kernel(float* __restrict__ out) {
    int t = blockIdx.x;
    int b = t / CN;
    const float4* hh = (const float4*)(g_h + (size_t)t * CD);
    float4 v = hh[threadIdx.x];
    int s1 = g_s1[t];
    if (s1 >= 0) {
        float gg = g_g1[t];
        const float4* x1 = (const float4*)(g_xo + ((size_t)(g_e1[t]*CB + b)*CCAP + s1) * CD);
        float4 a = x1[threadIdx.x];
        v.x = fmaf(gg, a.x, v.x); v.y = fmaf(gg, a.y, v.y);
        v.z = fmaf(gg, a.z, v.z); v.w = fmaf(gg, a.w, v.w);
    }
    int s2 = g_s2[t];
    if (s2 >= 0) {
        float gg = g_g2[t];
        const float4* x2 = (const float4*)(g_xo + ((size_t)(g_e2[t]*CB + b)*CCAP + s2) * CD);
        float4 a = x2[threadIdx.x];
        v.x = fmaf(gg, a.x, v.x); v.y = fmaf(gg, a.y, v.y);
        v.z = fmaf(gg, a.z, v.z); v.w = fmaf(gg, a.w, v.w);
    }
    ((float4*)out)[(size_t)t * (CD/4) + threadIdx.x] = v;
}

// ---------------- aux loss ----------------
__global__ void loss_kernel(float* __restrict__ out, int out_size) {
    int tid = threadIdx.x;
    int b = tid >> 4, e = tid & 15;
    float proxy = 0.f;
    for (int n = 0; n < CN; n++) proxy += g_raw[((size_t)(b*CN + n))*CE + e];
    proxy /= (float)CN;
    float dens = (float)g_cnt1[b*CE + e] / (float)CN;
    float v = proxy * dens;
    __shared__ float red[128];
    red[tid] = v;
    __syncthreads();
    for (int s = 64; s; s >>= 1) {
        if (tid < s) red[tid] += red[tid + s];
        __syncthreads();
    }
    if (tid == 0) {
        float loss = red[0] / (float)(CB*CE) * (float)(CE*CE) * 0.01f;
        const int base = CBN*CD;
        if (out_size > base) out[base] = loss;
        for (int i = base + 1; i < out_size; i++) out[i] = 0.f;
    }
}

// ---------------- launcher ----------------
extern "C" void kernel_launch(void* const* d_in, const int* in_sizes, int n_in,
                              void* d_out, int out_size) {
    const float* hid   = (const float*)d_in[0];
    const int*   mask  = (const int*)d_in[1];
    const float* ln0   = (const float*)d_in[2];
    const float* Wq    = (const float*)d_in[3];
    const float* Wk    = (const float*)d_in[4];
    const float* Wv    = (const float*)d_in[5];
    const float* Wo    = (const float*)d_in[6];
    const float* ln1   = (const float*)d_in[7];
    const float* gw    = (const float*)d_in[8];
    const float* ew1   = (const float*)d_in[9];
    const float* ew2   = (const float*)d_in[10];
    float* out = (float*)d_out;

    float *p_h, *p_n2, *p_xo;
    __half *p_nh, *p_nl, *p_qkvh, *p_qkvl, *p_aoh, *p_aol;
    __half *p_wqkvh, *p_wqkvl, *p_woh, *p_wol;
    __half *p_xinh, *p_midh, *p_w1h, *p_w2h;
    cudaGetSymbolAddress((void**)&p_h,     g_h);
    cudaGetSymbolAddress((void**)&p_n2,    g_n2);
    cudaGetSymbolAddress((void**)&p_xo,    g_xo);
    cudaGetSymbolAddress((void**)&p_nh,    g_nh);
    cudaGetSymbolAddress((void**)&p_nl,    g_nl);
    cudaGetSymbolAddress((void**)&p_qkvh,  g_qkvh);
    cudaGetSymbolAddress((void**)&p_qkvl,  g_qkvl);
    cudaGetSymbolAddress((void**)&p_aoh,   g_aoh);
    cudaGetSymbolAddress((void**)&p_aol,   g_aol);
    cudaGetSymbolAddress((void**)&p_wqkvh, g_wqkvh);
    cudaGetSymbolAddress((void**)&p_wqkvl, g_wqkvl);
    cudaGetSymbolAddress((void**)&p_woh,   g_woh);
    cudaGetSymbolAddress((void**)&p_wol,   g_wol);
    cudaGetSymbolAddress((void**)&p_xinh,  g_xinh);
    cudaGetSymbolAddress((void**)&p_midh,  g_midh);
    cudaGetSymbolAddress((void**)&p_w1h,   g_w1h);
    cudaGetSymbolAddress((void**)&p_w2h,   g_w2h);

    cudaFuncSetAttribute(tc_attn, cudaFuncAttributeMaxDynamicSharedMemorySize, TCATTN_SMEM);

    // ---- weight prep ----
    convert_qkv_kernel<<<576, 256>>>(Wq, Wk, Wv, p_wqkvh, p_wqkvl);
    long nproj4 = (long)CD*CD/4;
    convert_kernel<true ><<<1024, 256>>>(Wo, p_woh, p_wol, nproj4, WSCALE);
    long nff4 = (long)CE*CD*CDFF/4;
    convert_kernel<false><<<8192, 256>>>(ew1, p_w1h, nullptr, nff4, 1.0f);
    convert_kernel<false><<<8192, 256>>>(ew2, p_w2h, nullptr, nff4, 1.0f);

    // 1. RMSNorm 0 -> split fp16
    rmsnorm_kernel<1><<<CBN, 256>>>(hid, ln0, nullptr, p_nh, p_nl);

    // 2. QKV projection: ONE fused split-fp16 GEMM, Nn=2304 (1152 CTAs = 3.9 waves)
    mma_gemm<3,false,false,2><<<dim3(QKVS/128, CBN/128, 1), 256>>>(
        p_nh, p_nl, p_wqkvh, p_wqkvl, nullptr, p_qkvh, p_qkvl, QKVS, CD, WISCALE, 0, 0, 0);

    // 3. tensor-core attention (reads combined qkv) -> split fp16 ao
    tc_attn<<<dim3(CN/128, CB*CH), 256, TCATTN_SMEM>>>(mask);

    // 4. output projection + residual -> h (fp32)
    mma_gemm<3,false,true,0><<<dim3(CD/128, CBN/128, 1), 256>>>(
        p_aoh, p_aol, p_woh, p_wol, hid, p_h, nullptr, CD, CD, WISCALE, 0, 0, 0);

    // 5. RMSNorm 1 -> fp32
    rmsnorm_kernel<0><<<CBN, 256>>>(p_h, ln1, p_n2, nullptr, nullptr);

    // 6. gating: fused logits+softmax+top2, then warp-scan capacity (incl. route init)
    gate_fused_kernel<<<CBN/16, 256>>>(gw);
    capacity_scan_kernel<<<16, 256>>>();

    // 7. dispatch (fp16)
    gather_h_kernel<<<CEC, CD/4>>>();

    // 8. expert FFN (fp16 mma, fp32 accum; validated 128x128 shape)
    mma_gemm<1,true,false,1><<<dim3(CDFF/128, CMZ/128, CE), 256>>>(
        p_xinh, nullptr, p_w1h, nullptr, nullptr, p_midh, nullptr, CDFF, CD, 1.0f,
        (long)CMZ*CD, (long)CD*CDFF, (long)CMZ*CDFF);
    mma_gemm<1,false,false,0><<<dim3(CD/128, CMZ/128, CE), 256>>>(
        p_midh, nullptr, p_w2h, nullptr, nullptr, p_xo, nullptr, CD, CDFF, 1.0f,
        (long)CMZ*CDFF, (long)CDFF*CD, (long)CMZ*CD);

    // 9. combine + residual 2
    combine_kernel<<<CBN, CD/4>>>(out);

    // 10. aux loss
    loss_kernel<<<1, 128>>>(out, out_size);
}

// round 16
// speedup vs baseline: 1.5915x; 1.2452x over previous
#include <cuda_runtime.h>
#include <cuda_fp16.h>
#include <cstdint>

// ---------------- problem constants ----------------
#define CB   8
#define CN   1024
#define CD   768
#define CH   12
#define CDKV 64
#define CDFF 3072
#define CE   16
#define CCAP 128
#define CBN  (CB*CN)          // 8192 tokens
#define CEC  (CE*CB*CCAP)     // 16384 expert slots
#define CMZ  (CB*CCAP)        // 1024 rows per expert
#define QKVS (3*CD)           // 2304: combined qkv row stride
#define WSCALE 32.0f
#define WISCALE (1.0f/32.0f)

// ---------------- device scratch ----------------
static __device__ float g_h      [CBN*CD];
static __device__ float g_n2     [CBN*CD];
static __device__ float g_raw    [CBN*CE];
static __device__ int   g_e1[CBN], g_e2[CBN], g_s1[CBN], g_s2[CBN];
static __device__ float g_g1[CBN], g_g2[CBN];
static __device__ int   g_cnt1[CB*CE];
static __device__ int   g_route[CEC];
static __device__ float g_xo [CEC*CD];
// fp16 activations
static __device__ __half g_nh  [CBN*CD];           // normed (fp16)
static __device__ __half g_qkvh[CBN*QKVS];         // combined q|k|v (fp16)
static __device__ __half g_aoh[CBN*CD], g_aol[CBN*CD];  // attn out hi/lo (split)
// fp16 projection weights, native [K][N], scaled by WSCALE
static __device__ __half g_wqkvh[CD*QKVS];              // combined Wq|Wk|Wv (fp16)
static __device__ __half g_woh[CD*CD], g_wol[CD*CD];    // Wo split hi/lo
// fp16 MoE path (weights native [K][N])
static __device__ __half g_xinh[CEC*CD];
static __device__ __half g_midh[CEC*CDFF];
static __device__ __half g_w1h [CE*CD*CDFF];   // [e][D][DFF]
static __device__ __half g_w2h [CE*CDFF*CD];   // [e][DFF][D]

// ================= portable PTX helpers =================
__device__ __forceinline__ uint32_t smem_u32(const void* p) {
    uint32_t a;
    asm("{ .reg .u64 t; cvta.to.shared.u64 t, %1; cvt.u32.u64 %0, t; }" : "=r"(a) : "l"(p));
    return a;
}
#define CP16(dst, src) \
    asm volatile("cp.async.cg.shared.global [%0], [%1], 16;" :: "r"(dst), "l"(src) : "memory")
#define CPCOMMIT() asm volatile("cp.async.commit_group;" ::: "memory")
#define CPWAIT0()  asm volatile("cp.async.wait_group 0;" ::: "memory")
#define LDSM4(r0, r1, r2, r3, addr) \
    asm volatile("ldmatrix.sync.aligned.m8n8.x4.shared.b16 {%0,%1,%2,%3}, [%4];" \
        : "=r"(r0), "=r"(r1), "=r"(r2), "=r"(r3) : "r"(addr))
#define LDSM4T(r0, r1, r2, r3, addr) \
    asm volatile("ldmatrix.sync.aligned.m8n8.x4.trans.shared.b16 {%0,%1,%2,%3}, [%4];" \
        : "=r"(r0), "=r"(r1), "=r"(r2), "=r"(r3) : "r"(addr))
#define MMAH(c, a, b0v, b1v) \
    asm volatile("mma.sync.aligned.m16n8k16.row.col.f32.f16.f16.f32 " \
        "{%0,%1,%2,%3}, {%4,%5,%6,%7}, {%8,%9}, {%0,%1,%2,%3};" \
        : "+f"((c)[0]), "+f"((c)[1]), "+f"((c)[2]), "+f"((c)[3]) \
        : "r"((a)[0]), "r"((a)[1]), "r"((a)[2]), "r"((a)[3]), "r"(b0v), "r"(b1v))

// FMA-pipe exp (no MUFU)
__device__ __forceinline__ float fast_exp(float x) {
    x = fmaxf(x, -80.f);
    float t  = x * 1.44269504f;
    float tt = t + 12582912.f;
    int   ei = __float_as_int(tt) - 0x4B400000;
    float n  = tt - 12582912.f;
    float f  = t - n;
    float u  = f * 0.69314718f;
    float p  = 1.f + u*(1.f + u*(0.5f + u*(0.16666667f + u*(0.041666668f +
               u*(0.0083333338f + u*0.0013888889f)))));
    return __int_as_float(__float_as_int(p) + (ei << 23));
}

// ---------------- RMSNorm; OUTMODE 0=fp32, 3=fp16 ----------------
template<int OUTMODE>
__global__ void rmsnorm_kernel(const float* __restrict__ x,
                               const float* __restrict__ w,
                               float* __restrict__ y,
                               __half* __restrict__ yh) {
    int row = blockIdx.x;
    const float* xr = x + (size_t)row * CD;
    float s = 0.f;
    for (int i = threadIdx.x; i < CD; i += 256) { float v = xr[i]; s = fmaf(v, v, s); }
    for (int o = 16; o; o >>= 1) s += __shfl_xor_sync(0xffffffffu, s, o);
    __shared__ float red[8];
    __shared__ float invs;
    if ((threadIdx.x & 31) == 0) red[threadIdx.x >> 5] = s;
    __syncthreads();
    if (threadIdx.x == 0) {
        float tot = 0.f;
        #pragma unroll
        for (int i = 0; i < 8; i++) tot += red[i];
        invs = rsqrtf(tot / CD + 1e-6f);
    }
    __syncthreads();
    float inv = invs;
    for (int i = threadIdx.x; i < CD; i += 256) {
        float v = xr[i] * inv * w[i];
        if (OUTMODE == 0) y[(size_t)row*CD + i] = v;
        else              yh[(size_t)row*CD + i] = __float2half_rn(v);
    }
}

// ---------------- unified fp16 tensor-core GEMM (2-stage, static smem) ----------------
template<int TERMS, bool RELU, bool RESID, int OUTM>
__global__ __launch_bounds__(256) void mma_gemm(
    const __half* __restrict__ Ahi, const __half* __restrict__ Alo,
    const __half* __restrict__ Bhi, const __half* __restrict__ Blo,
    const float* __restrict__ Rz, void* __restrict__ Cout, void* __restrict__ Cout2,
    int Nn, int K, float scale, long zA, long zB, long zC)
{
    constexpr int BK    = (TERMS == 3) ? 16 : 32;
    constexpr int NA    = (TERMS == 3) ? 2 : 1;
    constexpr int LDSA  = BK + 8;
    constexpr int LDSB  = 136;
    constexpr uint32_t ATILEB = 128u * LDSA * 2;
    constexpr uint32_t BTILEB = (uint32_t)BK * LDSB * 2;
    constexpr uint32_t STAGEB = NA * (ATILEB + BTILEB);
    constexpr int ACH = 128 * (BK / 8);
    constexpr int BCH = BK * 16;
    constexpr int CPT = NA * (ACH + BCH) / 256;
    __shared__ __align__(16) unsigned char sm[2 * STAGEB];

    long e = blockIdx.z;
    int m0 = blockIdx.y * 128, n0 = blockIdx.x * 128;

    int tid = threadIdx.x, lane = tid & 31, wid = tid >> 5;
    int warp_row = (wid & 3) * 32, warp_col = (wid >> 2) * 64;
    uint32_t sb = smem_u32(sm);

    const __half* cur[CPT];
    long gstep[CPT];
    uint32_t sd[CPT];
    #pragma unroll
    for (int j = 0; j < CPT; j++) {
        int c = tid + j * 256;
        if (c < NA * ACH) {
            int tile = c / ACH;
            int rr = (c % ACH) / (BK / 8);
            int c8 = c % (BK / 8);
            sd[j] = tile * (ATILEB + BTILEB) + (uint32_t)(rr * LDSA + c8 * 8) * 2;
            const __half* src = (tile == 0 ? Ahi : Alo);
            cur[j] = src + e * zA + (long)(m0 + rr) * K + c8 * 8;
            gstep[j] = BK;
        } else {
            int c2 = c - NA * ACH;
            int tile = c2 / BCH;
            int rr = (c2 % BCH) / 16;
            int c8 = c2 % 16;
            sd[j] = tile * (ATILEB + BTILEB) + ATILEB + (uint32_t)(rr * LDSB + c8 * 8) * 2;
            const __half* src = (tile == 0 ? Bhi : Blo);
            cur[j] = src + e * zB + (long)rr * Nn + n0 + c8 * 8;
            gstep[j] = (long)BK * Nn;
        }
    }

    int nk = K / BK;
    #pragma unroll
    for (int j = 0; j < CPT; j++) { CP16(sb + sd[j], cur[j]); cur[j] += gstep[j]; }
    CPCOMMIT();

    float acc[2][8][4];
    #pragma unroll
    for (int mi = 0; mi < 2; mi++)
        #pragma unroll
        for (int ni = 0; ni < 8; ni++)
            #pragma unroll
            for (int j = 0; j < 4; j++) acc[mi][ni][j] = 0.f;

    int lm_r = lane & 15, lm_k = (lane >> 4) << 3;

    for (int kc = 0; kc < nk; kc++) {
        CPWAIT0();
        __syncthreads();
        if (kc + 1 < nk) {
            uint32_t s2 = (uint32_t)((kc + 1) & 1) * STAGEB;
            #pragma unroll
            for (int j = 0; j < CPT; j++) { CP16(sb + s2 + sd[j], cur[j]); cur[j] += gstep[j]; }
            CPCOMMIT();
        }
        uint32_t st = sb + (uint32_t)(kc & 1) * STAGEB;
        #pragma unroll
        for (int k16 = 0; k16 < BK; k16 += 16) {
            uint32_t afh[2][4], afl[2][4];
            #pragma unroll
            for (int mi = 0; mi < 2; mi++) {
                int row = warp_row + mi*16 + lm_r;
                LDSM4(afh[mi][0], afh[mi][1], afh[mi][2], afh[mi][3],
                      st + (uint32_t)(row*LDSA + k16 + lm_k) * 2);
                if (TERMS == 3)
                    LDSM4(afl[mi][0], afl[mi][1], afl[mi][2], afl[mi][3],
                          st + (ATILEB + BTILEB) + (uint32_t)(row*LDSA + k16 + lm_k) * 2);
            }
            #pragma unroll
            for (int nt = 0; nt < 4; nt++) {
                uint32_t boff = (uint32_t)((k16 + lm_r) * LDSB + warp_col + nt*16 + lm_k) * 2;
                uint32_t bh[4], bl[4];
                LDSM4T(bh[0], bh[1], bh[2], bh[3], st + ATILEB + boff);
                if (TERMS == 3)
                    LDSM4T(bl[0], bl[1], bl[2], bl[3],
                           st + (ATILEB + BTILEB) + ATILEB + boff);
                #pragma unroll
                for (int mi = 0; mi < 2; mi++)
                    #pragma unroll
                    for (int hh = 0; hh < 2; hh++) {
                        float* cc = acc[mi][nt*2 + hh];
                        MMAH(cc, afh[mi], bh[2*hh], bh[2*hh + 1]);
                        if (TERMS == 3) {
                            MMAH(cc, afh[mi], bl[2*hh], bl[2*hh + 1]);
                            MMAH(cc, afl[mi], bh[2*hh], bh[2*hh + 1]);
                        }
                    }
            }
        }
    }

    int eg = lane >> 2, et = lane & 3;
    #pragma unroll
    for (int mi = 0; mi < 2; mi++) {
        #pragma unroll
        for (int ni = 0; ni < 8; ni++) {
            long r  = m0 + warp_row + mi*16 + eg;
            long cc = n0 + warp_col + ni*8 + et*2;
            float v0 = acc[mi][ni][0]*scale, v1 = acc[mi][ni][1]*scale;
            float v2 = acc[mi][ni][2]*scale, v3 = acc[mi][ni][3]*scale;
            if (RESID) {
                float2 r0 = *(const float2*)(Rz + r*Nn + cc);
                float2 r1 = *(const float2*)(Rz + (r+8)*Nn + cc);
                v0 += r0.x; v1 += r0.y; v2 += r1.x; v3 += r1.y;
            }
            if (RELU) {
                v0 = fmaxf(v0, 0.f); v1 = fmaxf(v1, 0.f);
                v2 = fmaxf(v2, 0.f); v3 = fmaxf(v3, 0.f);
            }
            if (OUTM == 0) {
                float* C = (float*)Cout + e*zC;
                *(float2*)(C + r*Nn + cc)     = make_float2(v0, v1);
                *(float2*)(C + (r+8)*Nn + cc) = make_float2(v2, v3);
            } else if (OUTM == 1) {
                __half* C = (__half*)Cout + e*zC;
                *(__half2*)(C + r*Nn + cc)     = __floats2half2_rn(v0, v1);
                *(__half2*)(C + (r+8)*Nn + cc) = __floats2half2_rn(v2, v3);
            } else {
                __half* C  = (__half*)Cout  + e*zC;
                __half* C2 = (__half*)Cout2 + e*zC;
                __half2 h0 = __floats2half2_rn(v0, v1);
                float2 f0 = __half22float2(h0);
                *(__half2*)(C  + r*Nn + cc) = h0;
                *(__half2*)(C2 + r*Nn + cc) = __floats2half2_rn(v0 - f0.x, v1 - f0.y);
                __half2 h1 = __floats2half2_rn(v2, v3);
                float2 f1 = __half22float2(h1);
                *(__half2*)(C  + (r+8)*Nn + cc) = h1;
                *(__half2*)(C2 + (r+8)*Nn + cc) = __floats2half2_rn(v2 - f1.x, v3 - f1.y);
            }
        }
    }
}

// ---------------- tensor-core flash attention (plain fp16 MMA, fp32 softmax/accum) ----------------
// q/k/v from combined fp16 [token][2304] buffer. Output ao written split-fp16
// (hi+lo of the fp32 result) so the 3-term Wo projection keeps h fp32-accurate.
__global__ __launch_bounds__(256) void tc_attn(const int* __restrict__ mask) {
    extern __shared__ __align__(16) unsigned char sm[];
    constexpr uint32_t LDQ = 72;
    constexpr uint32_t QT  = 128*LDQ*2;    // 18432
    constexpr uint32_t KVT = 64*LDQ*2;     // 9216
    constexpr uint32_t KVS = 2*KVT;        // K + V per stage
    constexpr uint32_t KVB = QT;
    constexpr uint32_t MBB = KVB + 2*KVS;  // mask bias area

    int tid = threadIdx.x, lane = tid & 31, w = tid >> 5;
    int g = lane >> 2, t4 = lane & 3;
    int lm_r = lane & 15, lm_k = (lane >> 4) << 3;
    int bh = blockIdx.y, b = bh / CH, hh = bh % CH;
    int q0 = blockIdx.x * 128;
    uint32_t sb = smem_u32(sm);
    float* MBf = (float*)(sm + MBB);

    for (int i = tid; i < CN; i += 256)
        MBf[i] = (mask[b*CN + i] != 0) ? 0.f : -1e9f;

    // prologue: Q + KV stage 0 (fp16 only)
    #pragma unroll
    for (int j = 0; j < 4; j++) {
        int c = tid + j*256;                 // 0..1023
        int row = c >> 3, ch = c & 7;
        const __half* src = g_qkvh + (size_t)(b*CN + q0 + row)*QKVS + hh*CDKV + ch*8;
        CP16(sb + (uint32_t)(row*LDQ + ch*8)*2, src);
    }
    #pragma unroll
    for (int j = 0; j < 4; j++) {
        int c = tid + j*256;                 // 0..1023
        int arr = c >> 9, idx = c & 511;     // 0=K, 1=V
        int row = idx >> 3, ch = idx & 7;
        int part = (arr == 0) ? CD : 2*CD;
        const __half* src = g_qkvh + (size_t)(b*CN + row)*QKVS + part + hh*CDKV + ch*8;
        CP16(sb + KVB + (uint32_t)arr*KVT + (uint32_t)(row*LDQ + ch*8)*2, src);
    }
    CPCOMMIT();
    CPWAIT0();
    __syncthreads();

    uint32_t qf[4][4];
    #pragma unroll
    for (int kc = 0; kc < 4; kc++) {
        uint32_t a = sb + (uint32_t)((w*16 + lm_r)*LDQ + kc*16 + lm_k)*2;
        LDSM4(qf[kc][0], qf[kc][1], qf[kc][2], qf[kc][3], a);
    }

    float m_lo = -1e30f, m_hi = -1e30f, l_lo = 0.f, l_hi = 0.f;
    float o[8][4];
    #pragma unroll
    for (int nd = 0; nd < 8; nd++)
        #pragma unroll
        for (int j = 0; j < 4; j++) o[nd][j] = 0.f;

    for (int kt = 0; kt < 16; kt++) {
        if (kt > 0) { CPWAIT0(); __syncthreads(); }
        if (kt + 1 < 16) {
            uint32_t s2 = (uint32_t)((kt+1) & 1) * KVS;
            #pragma unroll
            for (int j = 0; j < 4; j++) {
                int c = tid + j*256;
                int arr = c >> 9, idx = c & 511;
                int row = idx >> 3, ch = idx & 7;
                int part = (arr == 0) ? CD : 2*CD;
                const __half* src = g_qkvh + (size_t)(b*CN + (kt+1)*64 + row)*QKVS + part + hh*CDKV + ch*8;
                CP16(sb + KVB + s2 + (uint32_t)arr*KVT + (uint32_t)(row*LDQ + ch*8)*2, src);
            }
            CPCOMMIT();
        }
        uint32_t kb = sb + KVB + (uint32_t)(kt & 1) * KVS;

        // S = Q K^T (1-term fp16)
        float cs[8][4];
        #pragma unroll
        for (int ni = 0; ni < 8; ni++)
            #pragma unroll
            for (int j = 0; j < 4; j++) cs[ni][j] = 0.f;
        #pragma unroll
        for (int kc = 0; kc < 4; kc++) {
            #pragma unroll
            for (int nt = 0; nt < 4; nt++) {
                uint32_t ka = kb + (uint32_t)((nt*16 + lm_r)*LDQ + kc*16 + lm_k)*2;
                uint32_t kf[4];
                LDSM4(kf[0], kf[1], kf[2], kf[3], ka);
                #pragma unroll
                for (int hx = 0; hx < 2; hx++)
                    MMAH(cs[nt*2 + hx], qf[kc], kf[hx], kf[2+hx]);
            }
        }
        float tl = -1e30f, th = -1e30f;
        #pragma unroll
        for (int ni = 0; ni < 8; ni++) {
            float b0 = MBf[kt*64 + ni*8 + 2*t4];
            float b1 = MBf[kt*64 + ni*8 + 2*t4 + 1];
            cs[ni][0] += b0; cs[ni][1] += b1; cs[ni][2] += b0; cs[ni][3] += b1;
            tl = fmaxf(tl, fmaxf(cs[ni][0], cs[ni][1]));
            th = fmaxf(th, fmaxf(cs[ni][2], cs[ni][3]));
        }
        tl = fmaxf(tl, __shfl_xor_sync(0xffffffffu, tl, 1));
        tl = fmaxf(tl, __shfl_xor_sync(0xffffffffu, tl, 2));
        th = fmaxf(th, __shfl_xor_sync(0xffffffffu, th, 1));
        th = fmaxf(th, __shfl_xor_sync(0xffffffffu, th, 2));
        float mn_lo = fmaxf(m_lo, tl), mn_hi = fmaxf(m_hi, th);
        float sc_lo = fast_exp(m_lo - mn_lo), sc_hi = fast_exp(m_hi - mn_hi);
        m_lo = mn_lo; m_hi = mn_hi;
        l_lo *= sc_lo; l_hi *= sc_hi;
        #pragma unroll
        for (int nd = 0; nd < 8; nd++) {
            o[nd][0] *= sc_lo; o[nd][1] *= sc_lo;
            o[nd][2] *= sc_hi; o[nd][3] *= sc_hi;
        }
        // p = exp(s - m), packed fp16 A-fragments (C-layout == A-layout identity)
        uint32_t pf[4][4];
        #pragma unroll
        for (int j = 0; j < 4; j++) {
            float a0 = fast_exp(cs[2*j][0] - mn_lo),   a1 = fast_exp(cs[2*j][1] - mn_lo);
            float a2 = fast_exp(cs[2*j][2] - mn_hi),   a3 = fast_exp(cs[2*j][3] - mn_hi);
            float b0 = fast_exp(cs[2*j+1][0] - mn_lo), b1 = fast_exp(cs[2*j+1][1] - mn_lo);
            float b2 = fast_exp(cs[2*j+1][2] - mn_hi), b3 = fast_exp(cs[2*j+1][3] - mn_hi);
            l_lo += (a0 + a1) + (b0 + b1);
            l_hi += (a2 + a3) + (b2 + b3);
            __half2 h;
            h = __floats2half2_rn(a0, a1); pf[j][0] = *(uint32_t*)&h;
            h = __floats2half2_rn(a2, a3); pf[j][1] = *(uint32_t*)&h;
            h = __floats2half2_rn(b0, b1); pf[j][2] = *(uint32_t*)&h;
            h = __floats2half2_rn(b2, b3); pf[j][3] = *(uint32_t*)&h;
        }
        // out += P V (1-term fp16); V tile [64 k][64 d] -> trans ldsm
        #pragma unroll
        for (int j = 0; j < 4; j++) {
            #pragma unroll
            for (int nt = 0; nt < 4; nt++) {
                uint32_t va = kb + KVT + (uint32_t)((j*16 + lm_r)*LDQ + nt*16 + lm_k)*2;
                uint32_t vf[4];
                LDSM4T(vf[0], vf[1], vf[2], vf[3], va);
                #pragma unroll
                for (int hx = 0; hx < 2; hx++)
                    MMAH(o[nt*2 + hx], pf[j], vf[2*hx], vf[2*hx+1]);
            }
        }
    }

    l_lo += __shfl_xor_sync(0xffffffffu, l_lo, 1);
    l_lo += __shfl_xor_sync(0xffffffffu, l_lo, 2);
    l_hi += __shfl_xor_sync(0xffffffffu, l_hi, 1);
    l_hi += __shfl_xor_sync(0xffffffffu, l_hi, 2);
    float il = 1.f / l_lo, ih = 1.f / l_hi;
    int r_lo = q0 + w*16 + g, r_hi = r_lo + 8;
    #pragma unroll
    for (int nd = 0; nd < 8; nd++) {
        int col = nd*8 + 2*t4;
        size_t o_lo = ((size_t)(b*CN + r_lo)*CH + hh)*CDKV + col;
        size_t o_hi = ((size_t)(b*CN + r_hi)*CH + hh)*CDKV + col;
        float v0 = o[nd][0]*il, v1 = o[nd][1]*il;
        float v2 = o[nd][2]*ih, v3 = o[nd][3]*ih;
        __half2 h0 = __floats2half2_rn(v0, v1);
        float2 f0 = __half22float2(h0);
        *(__half2*)(g_aoh + o_lo) = h0;
        *(__half2*)(g_aol + o_lo) = __floats2half2_rn(v0 - f0.x, v1 - f0.y);
        __half2 h1 = __floats2half2_rn(v2, v3);
        float2 f1 = __half22float2(h1);
        *(__half2*)(g_aoh + o_hi) = h1;
        *(__half2*)(g_aol + o_hi) = __floats2half2_rn(v2 - f1.x, v3 - f1.y);
    }
}
#define TCATTN_SMEM ((128*72*2) + 2*2*(64*72*2) + 1024*4)   // 59392

// ---------------- fused gate: logits + softmax + top2 (routing-exact) ----------------
__global__ void gate_fused_kernel(const float* __restrict__ gw) {
    int tid = threadIdx.x;
    int tok = blockIdx.x * 16 + (tid >> 4);
    int e = tid & 15;
    const float* xr = g_n2 + (size_t)tok * CD;
    float acc = 0.f;
    #pragma unroll 8
    for (int d = 0; d < CD; d++) acc = fmaf(xr[d], gw[d*CE + e], acc);
    float mx = acc;
    #pragma unroll
    for (int o = 8; o; o >>= 1) mx = fmaxf(mx, __shfl_xor_sync(0xffffffffu, mx, o, 16));
    float ex = __expf(acc - mx);
    float sum = ex;
    #pragma unroll
    for (int o = 8; o; o >>= 1) sum += __shfl_xor_sync(0xffffffffu, sum, o, 16);
    float raw = ex / sum;
    g_raw[(size_t)tok*CE + e] = raw;
    float v1 = raw; int i1 = e;
    #pragma unroll
    for (int o = 8; o; o >>= 1) {
        float ov = __shfl_xor_sync(0xffffffffu, v1, o, 16);
        int   oi = __shfl_xor_sync(0xffffffffu, i1, o, 16);
        if (ov > v1 || (ov == v1 && oi < i1)) { v1 = ov; i1 = oi; }
    }
    float v2 = (e == i1) ? -1.f : raw; int i2 = e;
    #pragma unroll
    for (int o = 8; o; o >>= 1) {
        float ov = __shfl_xor_sync(0xffffffffu, v2, o, 16);
        int   oi = __shfl_xor_sync(0xffffffffu, i2, o, 16);
        if (ov > v2 || (ov == v2 && oi < i2)) { v2 = ov; i2 = oi; }
    }
    if (e == 0) {
        float denom = v1 + v2 + 1e-9f;
        g_e1[tok] = i1; g_e2[tok] = i2;
        g_g1[tok] = v1 / denom; g_g2[tok] = v2 / denom;
    }
}

// ---------------- capacity assignment: warp-ballot prefix scan per (b,e) ----------------
__global__ void capacity_scan_kernel() {
    int w = (blockIdx.x * blockDim.x + threadIdx.x) >> 5;   // 0..127
    int lane = threadIdx.x & 31;
    int b = w >> 4, e = w & 15;
    unsigned lmlt = (1u << lane) - 1u;
    int base = (e*CB + b)*CCAP;

    int cnt = 0;
    for (int c = 0; c < CN/32; c++) {
        int t = b*CN + c*32 + lane;
        bool m = (g_e1[t] == e);
        unsigned bal = __ballot_sync(0xffffffffu, m);
        int pos = cnt + __popc(bal & lmlt);
        if (m) {
            if (pos < CCAP) { g_s1[t] = pos; g_route[base + pos] = t; }
            else            { g_s1[t] = -1; g_g1[t] = 0.f; }
        }
        cnt += __popc(bal);
    }
    if (lane == 0) g_cnt1[b*CE + e] = cnt;
    int m1c = cnt < CCAP ? cnt : CCAP;

    int cnt2 = 0;
    for (int c = 0; c < CN/32; c++) {
        int t = b*CN + c*32 + lane;
        bool m = (g_e2[t] == e);
        unsigned bal = __ballot_sync(0xffffffffu, m);
        int pos = m1c + cnt2 + __popc(bal & lmlt);
        if (m) {
            if (pos < CCAP) { g_s2[t] = pos; g_route[base + pos] = t; }
            else            { g_s2[t] = -1; g_g2[t] = 0.f; }
        }
        cnt2 += __popc(bal);
    }
    int fend = m1c + cnt2; if (fend > CCAP) fend = CCAP;
    for (int i = fend + lane; i < CCAP; i += 32) g_route[base + i] = -1;
}

// ---------------- gather tokens into expert slots (fp16 out) ----------------
__global__ void gather_h_kernel() {
    int row = blockIdx.x;
    int t = g_route[row];
    __half2* dst = (__half2*)(g_xinh + (size_t)row * CD);
    int i = threadIdx.x;
    if (t < 0) {
        __half2 z = __floats2half2_rn(0.f, 0.f);
        dst[2*i] = z; dst[2*i+1] = z;
    } else {
        float4 v = ((const float4*)(g_n2 + (size_t)t * CD))[i];
        dst[2*i]   = __floats2half2_rn(v.x, v.y);
        dst[2*i+1] = __floats2half2_rn(v.z, v.w);
    }
}

// ---------------- streaming fp32 -> fp16 convert ----------------
template<bool SPLIT>
__global__ void convert_kernel(const float* __restrict__ in,
                               __half* __restrict__ hi,
                               __half* __restrict__ lo,
                               long n4, float scale) {
    long i = (long)blockIdx.x * blockDim.x + threadIdx.x;
    long stride = (long)gridDim.x * blockDim.x;
    for (; i < n4; i += stride) {
        float4 v = ((const float4*)in)[i];
        v.x *= scale; v.y *= scale; v.z *= scale; v.w *= scale;
        __half2 h0 = __floats2half2_rn(v.x, v.y);
        __half2 h1 = __floats2half2_rn(v.z, v.w);
        ((__half2*)hi)[2*i]   = h0;
        ((__half2*)hi)[2*i+1] = h1;
        if (SPLIT) {
            float2 f0 = __half22float2(h0), f1 = __half22float2(h1);
            ((__half2*)lo)[2*i]   = __floats2half2_rn(v.x - f0.x, v.y - f0.y);
            ((__half2*)lo)[2*i+1] = __floats2half2_rn(v.z - f1.x, v.w - f1.y);
        }
    }
}

// ---------------- combined QKV weight convert (fp16 hi only) into [768][2304] ----------------
__global__ void convert_qkv_kernel(const float* __restrict__ Wq,
                                   const float* __restrict__ Wk,
                                   const float* __restrict__ Wv,
                                   __half* __restrict__ hi) {
    const long n4 = (long)CD*CD/4;
    long i = (long)blockIdx.x * blockDim.x + threadIdx.x;
    long stride = (long)gridDim.x * blockDim.x;
    for (; i < n4; i += stride) {
        long elem = i * 4;
        long k = elem / CD, n = elem % CD;
        size_t obase = (size_t)k * QKVS + n;
        #pragma unroll
        for (int part = 0; part < 3; part++) {
            const float* W = (part == 0 ? Wq : part == 1 ? Wk : Wv);
            float4 v = ((const float4*)W)[i];
            v.x *= WSCALE; v.y *= WSCALE; v.z *= WSCALE; v.w *= WSCALE;
            size_t o = obase + (size_t)part * CD;
            *(__half2*)(hi + o)     = __floats2half2_rn(v.x, v.y);
            *(__half2*)(hi + o + 2) = __floats2half2_rn(v.z, v.w);
        }
    }
}

// ---------------- weighted combine + residual 2 ----------------
__global__ void combine_kernel(float* __restrict__ out) {
    int t = blockIdx.x;
    int b = t / CN;
    const float4* hh = (const float4*)(g_h + (size_t)t * CD);
    float4 v = hh[threadIdx.x];
    int s1 = g_s1[t];
    if (s1 >= 0) {
        float gg = g_g1[t];
        const float4* x1 = (const float4*)(g_xo + ((size_t)(g_e1[t]*CB + b)*CCAP + s1) * CD);
        float4 a = x1[threadIdx.x];
        v.x = fmaf(gg, a.x, v.x); v.y = fmaf(gg, a.y, v.y);
        v.z = fmaf(gg, a.z, v.z); v.w = fmaf(gg, a.w, v.w);
    }
    int s2 = g_s2[t];
    if (s2 >= 0) {
        float gg = g_g2[t];
        const float4* x2 = (const float4*)(g_xo + ((size_t)(g_e2[t]*CB + b)*CCAP + s2) * CD);
        float4 a = x2[threadIdx.x];
        v.x = fmaf(gg, a.x, v.x); v.y = fmaf(gg, a.y, v.y);
        v.z = fmaf(gg, a.z, v.z); v.w = fmaf(gg, a.w, v.w);
    }
    ((float4*)out)[(size_t)t * (CD/4) + threadIdx.x] = v;
}

// ---------------- aux loss ----------------
__global__ void loss_kernel(float* __restrict__ out, int out_size) {
    int tid = threadIdx.x;
    int b = tid >> 4, e = tid & 15;
    float proxy = 0.f;
    for (int n = 0; n < CN; n++) proxy += g_raw[((size_t)(b*CN + n))*CE + e];
    proxy /= (float)CN;
    float dens = (float)g_cnt1[b*CE + e] / (float)CN;
    float v = proxy * dens;
    __shared__ float red[128];
    red[tid] = v;
    __syncthreads();
    for (int s = 64; s; s >>= 1) {
        if (tid < s) red[tid] += red[tid + s];
        __syncthreads();
    }
    if (tid == 0) {
        float loss = red[0] / (float)(CB*CE) * (float)(CE*CE) * 0.01f;
        const int base = CBN*CD;
        if (out_size > base) out[base] = loss;
        for (int i = base + 1; i < out_size; i++) out[i] = 0.f;
    }
}

// ---------------- launcher ----------------
extern "C" void kernel_launch(void* const* d_in, const int* in_sizes, int n_in,
                              void* d_out, int out_size) {
    const float* hid   = (const float*)d_in[0];
    const int*   mask  = (const int*)d_in[1];
    const float* ln0   = (const float*)d_in[2];
    const float* Wq    = (const float*)d_in[3];
    const float* Wk    = (const float*)d_in[4];
    const float* Wv    = (const float*)d_in[5];
    const float* Wo    = (const float*)d_in[6];
    const float* ln1   = (const float*)d_in[7];
    const float* gw    = (const float*)d_in[8];
    const float* ew1   = (const float*)d_in[9];
    const float* ew2   = (const float*)d_in[10];
    float* out = (float*)d_out;

    float *p_h, *p_n2, *p_xo;
    __half *p_nh, *p_qkvh, *p_aoh, *p_aol;
    __half *p_wqkvh, *p_woh, *p_wol;
    __half *p_xinh, *p_midh, *p_w1h, *p_w2h;
    cudaGetSymbolAddress((void**)&p_h,     g_h);
    cudaGetSymbolAddress((void**)&p_n2,    g_n2);
    cudaGetSymbolAddress((void**)&p_xo,    g_xo);
    cudaGetSymbolAddress((void**)&p_nh,    g_nh);
    cudaGetSymbolAddress((void**)&p_qkvh,  g_qkvh);
    cudaGetSymbolAddress((void**)&p_aoh,   g_aoh);
    cudaGetSymbolAddress((void**)&p_aol,   g_aol);
    cudaGetSymbolAddress((void**)&p_wqkvh, g_wqkvh);
    cudaGetSymbolAddress((void**)&p_woh,   g_woh);
    cudaGetSymbolAddress((void**)&p_wol,   g_wol);
    cudaGetSymbolAddress((void**)&p_xinh,  g_xinh);
    cudaGetSymbolAddress((void**)&p_midh,  g_midh);
    cudaGetSymbolAddress((void**)&p_w1h,   g_w1h);
    cudaGetSymbolAddress((void**)&p_w2h,   g_w2h);

    cudaFuncSetAttribute(tc_attn, cudaFuncAttributeMaxDynamicSharedMemorySize, TCATTN_SMEM);

    // ---- weight prep ----
    convert_qkv_kernel<<<576, 256>>>(Wq, Wk, Wv, p_wqkvh);
    long nproj4 = (long)CD*CD/4;
    convert_kernel<true ><<<1024, 256>>>(Wo, p_woh, p_wol, nproj4, WSCALE);
    long nff4 = (long)CE*CD*CDFF/4;
    convert_kernel<false><<<8192, 256>>>(ew1, p_w1h, nullptr, nff4, 1.0f);
    convert_kernel<false><<<8192, 256>>>(ew2, p_w2h, nullptr, nff4, 1.0f);

    // 1. RMSNorm 0 -> fp16
    rmsnorm_kernel<3><<<CBN, 256>>>(hid, ln0, nullptr, p_nh);

    // 2. QKV projection: ONE plain-fp16 GEMM, Nn=2304
    mma_gemm<1,false,false,1><<<dim3(QKVS/128, CBN/128, 1), 256>>>(
        p_nh, nullptr, p_wqkvh, nullptr, nullptr, p_qkvh, nullptr, QKVS, CD, WISCALE, 0, 0, 0);

    // 3. tensor-core attention (fp16 MMA, fp32 softmax) -> split fp16 ao
    tc_attn<<<dim3(CN/128, CB*CH), 256, TCATTN_SMEM>>>(mask);

    // 4. output projection + residual -> h (fp32; 3-term keeps h/routing accurate)
    mma_gemm<3,false,true,0><<<dim3(CD/128, CBN/128, 1), 256>>>(
        p_aoh, p_aol, p_woh, p_wol, hid, p_h, nullptr, CD, CD, WISCALE, 0, 0, 0);

    // 5. RMSNorm 1 -> fp32
    rmsnorm_kernel<0><<<CBN, 256>>>(p_h, ln1, p_n2, nullptr);

    // 6. gating: fused logits+softmax+top2, then warp-scan capacity
    gate_fused_kernel<<<CBN/16, 256>>>(gw);
    capacity_scan_kernel<<<16, 256>>>();

    // 7. dispatch (fp16)
    gather_h_kernel<<<CEC, CD/4>>>();

    // 8. expert FFN (fp16 mma, fp32 accum; validated 128x128 shape)
    mma_gemm<1,true,false,1><<<dim3(CDFF/128, CMZ/128, CE), 256>>>(
        p_xinh, nullptr, p_w1h, nullptr, nullptr, p_midh, nullptr, CDFF, CD, 1.0f,
        (long)CMZ*CD, (long)CD*CDFF, (long)CMZ*CDFF);
    mma_gemm<1,false,false,0><<<dim3(CD/128, CMZ/128, CE), 256>>>(
        p_midh, nullptr, p_w2h, nullptr, nullptr, p_xo, nullptr, CD, CDFF, 1.0f,
        (long)CMZ*CDFF, (long)CDFF*CD, (long)CMZ*CD);

    // 9. combine + residual 2
    combine_kernel<<<CBN, CD/4>>>(out);

    // 10. aux loss
    loss_kernel<<<1, 128>>>(out, out_size);
}